// round 13
// baseline (speedup 1.0000x reference)
#include <cuda_runtime.h>
#include <cuda_bf16.h>
#include <cstdint>

#define NB 32
#define C 128
#define HW 3136
#define K3 384
#define NSPLIT 3
#define SPL ((size_t)NB * C * K3)

// A tiles: 128 rows x [hi 32 | lo 32] bf16 = 128B + 16 pad = 144B stride
#define RS 144
#define TILE_A (128 * RS)                     // 18432
// gemm2 B tile (transposed): 64 rows (hi 32 + lo 32) x 128 p-cols = 256B + 16 pad
#define RSB 272
#define TILE_B2 (64 * RSB)                    // 17408
#define STAGE1 (2 * TILE_A)
#define STAGE2 (TILE_A + TILE_B2)
#define SMEM1 (2 * STAGE1 + 1024)
#define SMEM2 (2 * STAGE2 + 1024)

#define G2_TILES 800                          // 32 batches x 25 p-tiles
#define G2_GRID 592                           // 148 SM x 2 CTAs

__device__ float g_t8[NB * 4 * HW];
__device__ float g_t7p[NSPLIT * NB * C * K3];
__device__ __nv_bfloat16 g_t6hi[(size_t)NB * C * HW];
__device__ __nv_bfloat16 g_t6lo[(size_t)NB * C * HW];
__device__ __nv_bfloat16 g_t7hi[(size_t)NB * C * K3];
__device__ __nv_bfloat16 g_t7lo[(size_t)NB * C * K3];
__device__ int g_ticket;                      // gemm2 work-stealing counter

// ---------------- helpers ----------------
__device__ __forceinline__ uint32_t smem_u32(const void* p) {
    uint32_t a;
    asm("{ .reg .u64 t; cvta.to.shared.u64 t, %1; cvt.u32.u64 %0, t; }" : "=r"(a) : "l"(p));
    return a;
}
#define CP16(dst, src) \
    asm volatile("cp.async.cg.shared.global [%0], [%1], 16;" :: "r"(dst), "l"(src))
#define CP_COMMIT() asm volatile("cp.async.commit_group;" ::: "memory")
#define CP_WAIT0()  asm volatile("cp.async.wait_group 0;" ::: "memory")
#define PF_L2(p)    asm volatile("prefetch.global.L2 [%0];" :: "l"(p))

__device__ __forceinline__ void ldsm4(uint32_t addr, uint32_t* r) {
    asm volatile("ldmatrix.sync.aligned.m8n8.x4.shared.b16 {%0,%1,%2,%3}, [%4];"
                 : "=r"(r[0]), "=r"(r[1]), "=r"(r[2]), "=r"(r[3]) : "r"(addr));
}
__device__ __forceinline__ void ldsm4t(uint32_t addr, uint32_t* r) {
    asm volatile("ldmatrix.sync.aligned.m8n8.x4.trans.shared.b16 {%0,%1,%2,%3}, [%4];"
                 : "=r"(r[0]), "=r"(r[1]), "=r"(r[2]), "=r"(r[3]) : "r"(addr));
}
__device__ __forceinline__ void mma16816(float* c, const uint32_t a[4],
                                         uint32_t b0, uint32_t b1) {
    asm volatile(
        "mma.sync.aligned.m16n8k16.row.col.f32.bf16.bf16.f32 "
        "{%0,%1,%2,%3}, {%4,%5,%6,%7}, {%8,%9}, {%0,%1,%2,%3};"
        : "+f"(c[0]), "+f"(c[1]), "+f"(c[2]), "+f"(c[3])
        : "r"(a[0]), "r"(a[1]), "r"(a[2]), "r"(a[3]), "r"(b0), "r"(b1));
}
__device__ __forceinline__ void split4(const float v[4], uint2& hi, uint2& lo) {
    __nv_bfloat16 h0 = __float2bfloat16(v[0]), h1 = __float2bfloat16(v[1]);
    __nv_bfloat16 h2 = __float2bfloat16(v[2]), h3 = __float2bfloat16(v[3]);
    __nv_bfloat16 l0 = __float2bfloat16(v[0] - __bfloat162float(h0));
    __nv_bfloat16 l1 = __float2bfloat16(v[1] - __bfloat162float(h1));
    __nv_bfloat16 l2 = __float2bfloat16(v[2] - __bfloat162float(h2));
    __nv_bfloat16 l3 = __float2bfloat16(v[3] - __bfloat162float(h3));
    hi.x = (uint32_t)__bfloat16_as_ushort(h0) | ((uint32_t)__bfloat16_as_ushort(h1) << 16);
    hi.y = (uint32_t)__bfloat16_as_ushort(h2) | ((uint32_t)__bfloat16_as_ushort(h3) << 16);
    lo.x = (uint32_t)__bfloat16_as_ushort(l0) | ((uint32_t)__bfloat16_as_ushort(l1) << 16);
    lo.y = (uint32_t)__bfloat16_as_ushort(l2) | ((uint32_t)__bfloat16_as_ushort(l3) << 16);
}

// cp.async one A tile: 128 rows x [hi 64B | lo 64B] from packed bf16 planes
__device__ __forceinline__ void cpA(char* Asp, const __nv_bfloat16* hi,
                                    const __nv_bfloat16* lo, size_t rstride,
                                    int col0, int tid) {
    #pragma unroll
    for (int it = 0; it < 2; it++) {
        int idx = tid + it * 256;
        int r = idx >> 2, s = idx & 3;
        CP16(smem_u32(Asp + r * RS + s * 16),
             hi + (size_t)r * rstride + col0 + s * 8);
    }
    #pragma unroll
    for (int it = 0; it < 2; it++) {
        int idx = tid + it * 256;
        int r = idx >> 2, s = idx & 3;
        CP16(smem_u32(Asp + r * RS + 64 + s * 16),
             lo + (size_t)r * rstride + col0 + s * 8);
    }
}

// 3 product passes over preloaded fragments
#define MMA_PASSES(acc, ah, al, bh, bl, ldA_lo)                         \
    do {                                                                \
        _Pragma("unroll")                                               \
        for (int mi = 0; mi < 2; mi++)                                  \
            _Pragma("unroll")                                           \
            for (int nq = 0; nq < 4; nq++) {                            \
                mma16816(acc[mi][nq * 2],     ah[mi], bh[nq][0], bh[nq][1]); \
                mma16816(acc[mi][nq * 2 + 1], ah[mi], bh[nq][2], bh[nq][3]); \
            }                                                           \
        _Pragma("unroll")                                               \
        for (int mi = 0; mi < 2; mi++)                                  \
            _Pragma("unroll")                                           \
            for (int nq = 0; nq < 4; nq++) {                            \
                mma16816(acc[mi][nq * 2],     ah[mi], bl[nq][0], bl[nq][1]); \
                mma16816(acc[mi][nq * 2 + 1], ah[mi], bl[nq][2], bl[nq][3]); \
            }                                                           \
        ldA_lo;                                                         \
        _Pragma("unroll")                                               \
        for (int mi = 0; mi < 2; mi++)                                  \
            _Pragma("unroll")                                           \
            for (int nq = 0; nq < 4; nq++) {                            \
                mma16816(acc[mi][nq * 2],     al[mi], bh[nq][0], bh[nq][1]); \
                mma16816(acc[mi][nq * 2 + 1], al[mi], bh[nq][2], bh[nq][3]); \
            }                                                           \
    } while (0)

__device__ __forceinline__ void mma_g1(uint32_t As, uint32_t Bs, int wr, int wc,
                                       int lane, float acc[2][8][4]) {
    const uint32_t a_row = (uint32_t)(wr * 32 + (lane & 15)) * RS + ((lane >> 4) << 4);
    const int brow = (lane & 7) + ((lane & 16) >> 1);
    const uint32_t b_k = (uint32_t)((lane & 8) << 1);
    #pragma unroll
    for (int ks = 0; ks < 2; ks++) {
        uint32_t k16 = ks * 32;
        uint32_t ah[2][4], al[2][4], bh[4][4], bl[4][4];
        #pragma unroll
        for (int mi = 0; mi < 2; mi++)
            ldsm4(As + a_row + (uint32_t)(mi * 16) * RS + k16, ah[mi]);
        #pragma unroll
        for (int nq = 0; nq < 4; nq++) {
            uint32_t bbase = Bs + (uint32_t)(wc * 64 + nq * 16 + brow) * RS + k16 + b_k;
            ldsm4(bbase,      bh[nq]);
            ldsm4(bbase + 64, bl[nq]);
        }
        MMA_PASSES(acc, ah, al, bh, bl,
            { _Pragma("unroll")
              for (int mi = 0; mi < 2; mi++)
                  ldsm4(As + a_row + (uint32_t)(mi * 16) * RS + k16 + 64, al[mi]); });
    }
}

__device__ __forceinline__ void mma_g2(uint32_t As, uint32_t Bs, int wr, int wc,
                                       int lane, float acc[2][8][4]) {
    const uint32_t a_row = (uint32_t)(wr * 32 + (lane & 15)) * RS + ((lane >> 4) << 4);
    const uint32_t b_row = (uint32_t)((lane & 7) + (lane & 8));
    const uint32_t b_pofs = (uint32_t)((lane & 16));
    #pragma unroll
    for (int ks = 0; ks < 2; ks++) {
        uint32_t k16 = ks * 32;
        uint32_t mb = ks * 16;
        uint32_t ah[2][4], al[2][4], bh[4][4], bl[4][4];
        #pragma unroll
        for (int mi = 0; mi < 2; mi++)
            ldsm4(As + a_row + (uint32_t)(mi * 16) * RS + k16, ah[mi]);
        #pragma unroll
        for (int nq = 0; nq < 4; nq++) {
            uint32_t addr = Bs + (mb + b_row) * RSB
                          + (uint32_t)(wc * 64 + nq * 16) * 2 + b_pofs;
            ldsm4t(addr,            bh[nq]);
            ldsm4t(addr + 32 * RSB, bl[nq]);
        }
        MMA_PASSES(acc, ah, al, bh, bl,
            { _Pragma("unroll")
              for (int mi = 0; mi < 2; mi++)
                  ldsm4(As + a_row + (uint32_t)(mi * 16) * RS + k16 + 64, al[mi]); });
    }
}

// ---------------------------------------------------------------------------
// prep: t8 reduction + packed t6 hi/lo planes. grid (98, 32) x 256
// ---------------------------------------------------------------------------
__global__ void __launch_bounds__(256) prep_kernel(const float* __restrict__ x,
                                                   const float* __restrict__ p5w,
                                                   const float* __restrict__ conv_w) {
    __shared__ float red[8][4][32];
    int n = blockIdx.y;
    int tid = threadIdx.x;
    int pl = tid & 31, q = tid >> 5;
    int p = blockIdx.x * 32 + pl;
    int rp = (p >= 56) ? (p - 56) : (p + 3080);

    const float* xb = x + (size_t)n * C * HW;
    __nv_bfloat16* t6h = g_t6hi + (size_t)n * C * HW;
    __nv_bfloat16* t6l = g_t6lo + (size_t)n * C * HW;

    float s0 = 0.f, s1 = 0.f, s2 = 0.f, s3 = 0.f;
    int c0 = q * 16;
    #pragma unroll 4
    for (int i = 0; i < 16; i++) {
        int c = c0 + i;
        float xp = xb[(size_t)c * HW + p];
        float xr = xb[(size_t)c * HW + rp];
        float v = xp + xr;
        __nv_bfloat16 h = __float2bfloat16(v);
        t6h[(size_t)c * HW + p] = h;
        t6l[(size_t)c * HW + p] = __float2bfloat16(v - __bfloat162float(h));
        float t = __ldg(&p5w[c]) * xr;
        s0 = fmaf(__ldg(&conv_w[c]),       t, s0);
        s1 = fmaf(__ldg(&conv_w[128 + c]), t, s1);
        s2 = fmaf(__ldg(&conv_w[256 + c]), t, s2);
        s3 = fmaf(__ldg(&conv_w[384 + c]), t, s3);
    }
    red[q][0][pl] = s0; red[q][1][pl] = s1; red[q][2][pl] = s2; red[q][3][pl] = s3;
    __syncthreads();
    if (tid < 128) {
        int j = tid >> 5, pl2 = tid & 31;
        float r = 0.f;
        #pragma unroll
        for (int qq = 0; qq < 8; qq++) r += red[qq][j][pl2];
        g_t8[((size_t)n * 4 + j) * HW + blockIdx.x * 32 + pl2] = r;
    }
}

// ---------------------------------------------------------------------------
// gemm1: D rows = c' (A = t6 planes via cp.async), cols = m. K chunks of 32.
// grid (3, 32, 3) x 256, occ 2. p2w prefetched 2 chunks ahead into L2.
// ---------------------------------------------------------------------------
__device__ __forceinline__ void g1_stageB(char* Bsp, const float* xb,
                                          const float* p2w, int m0, int p0, int tid) {
    int col4 = (tid & 7) * 4;
    int rbase = tid >> 3;
    #pragma unroll
    for (int pass = 0; pass < 4; pass++) {
        int mr = rbase + pass * 32;
        int m = m0 + mr, c = m / 3, k = m - 3 * c, sh = 2 * k - 2;
        float4 w4 = *reinterpret_cast<const float4*>(p2w + (size_t)m * HW + p0 + col4);
        int p = p0 + col4;
        int hh = p / 56 + sh;
        float v[4] = {0.f, 0.f, 0.f, 0.f};
        if (hh >= 0 && hh < 56) {
            float4 x4 = *reinterpret_cast<const float4*>(
                xb + (size_t)c * HW + p + sh * 56);
            v[0] = w4.x * x4.x; v[1] = w4.y * x4.y;
            v[2] = w4.z * x4.z; v[3] = w4.w * x4.w;
        }
        uint2 hi, lo; split4(v, hi, lo);
        char* bb = Bsp + mr * RS + col4 * 2;
        *(uint2*)(bb)      = hi;
        *(uint2*)(bb + 64) = lo;
    }
}

__global__ void __launch_bounds__(256, 2) gemm1_kernel(const float* __restrict__ x,
                                                       const float* __restrict__ p2w) {
    extern __shared__ char smem_raw[];
    char* smp = (char*)(((uintptr_t)smem_raw + 1023) & ~(uintptr_t)1023);

    const int tid = threadIdx.x, lane = tid & 31, wid = tid >> 5;
    const int wr = wid >> 1, wc = wid & 1;
    const int n = blockIdx.y, m0 = blockIdx.x * 128, s = blockIdx.z;

    const float* xb = x + (size_t)n * C * HW;
    const __nv_bfloat16* t6h = g_t6hi + (size_t)n * C * HW;
    const __nv_bfloat16* t6l = g_t6lo + (size_t)n * C * HW;

    float acc[2][8][4] = {};
    const int beg[4] = {0, 33, 66, 98};
    const int nch = beg[s + 1] - beg[s];
    const int pbase = beg[s] * 32;

    cpA(smp, t6h, t6l, HW, pbase, tid);
    CP_COMMIT();
    g1_stageB(smp + TILE_A, xb, p2w, m0, pbase, tid);
    CP_WAIT0();
    __syncthreads();

    for (int ch = 0; ch < nch; ch++) {
        char* cur = smp + (ch & 1) * STAGE1;
        bool more = ch + 1 < nch;
        char* nxt = smp + ((ch + 1) & 1) * STAGE1;
        int pn = pbase + (ch + 1) * 32;
        if (more) { cpA(nxt, t6h, t6l, HW, pn, tid); CP_COMMIT(); }
        // prefetch p2w lines for chunk ch+2 (one 128B line per m-row)
        if (ch + 2 < nch && tid < 128)
            PF_L2(p2w + (size_t)(m0 + tid) * HW + pbase + (ch + 2) * 32);
        mma_g1(smem_u32(cur), smem_u32(cur + TILE_A), wr, wc, lane, acc);
        if (more) g1_stageB(nxt + TILE_A, xb, p2w, m0, pn, tid);
        CP_WAIT0();
        __syncthreads();
    }

    const float SC = 9.1126371e-4f;   // 1/(sqrt(3136)*sqrt(384))
    float* ob = g_t7p + ((size_t)(s * NB + n)) * C * K3;
    #pragma unroll
    for (int mi = 0; mi < 2; mi++) {
        #pragma unroll
        for (int ni = 0; ni < 8; ni++) {
            int row = wr * 32 + mi * 16 + (lane >> 2);
            int col = m0 + wc * 64 + ni * 8 + (lane & 3) * 2;
            *(float2*)(ob + (size_t)row * K3 + col) =
                make_float2(acc[mi][ni][0] * SC, acc[mi][ni][1] * SC);
            *(float2*)(ob + (size_t)(row + 8) * K3 + col) =
                make_float2(acc[mi][ni][2] * SC, acc[mi][ni][3] * SC);
        }
    }
}

// ---------------------------------------------------------------------------
// t7sum: sum 3 partials, pack to hi/lo planes; reset gemm2 ticket. grid 1536
// ---------------------------------------------------------------------------
__global__ void __launch_bounds__(256) t7sum_kernel() {
    if (blockIdx.x == 0 && threadIdx.x == 0) g_ticket = G2_GRID;
    size_t i = ((size_t)blockIdx.x * 256 + threadIdx.x) * 4;
    float4 v0 = *(const float4*)(g_t7p + i);
    float4 v1 = *(const float4*)(g_t7p + SPL + i);
    float4 v2 = *(const float4*)(g_t7p + 2 * SPL + i);
    float v[4] = {v0.x + v1.x + v2.x, v0.y + v1.y + v2.y,
                  v0.z + v1.z + v2.z, v0.w + v1.w + v2.w};
    uint2 hi, lo; split4(v, hi, lo);
    *(uint2*)(g_t7hi + i) = hi;
    *(uint2*)(g_t7lo + i) = lo;
}

// ---------------------------------------------------------------------------
// gemm2: persistent with atomic work-stealing over 800 (n, p-tile) tiles.
// grid 592 x 256, occ 2.
// ---------------------------------------------------------------------------
__device__ __forceinline__ void g2_stageB(char* Bsp, const float* xb,
                                          int p0, int m0c, int tid) {
    int mrow = tid & 31;
    int pq = tid >> 5;
    int m = m0c + mrow, cp = m / 3, k = m - 3 * cp, sh = 2 * k - 2;
    int pbase = p0 + pq * 16;
    const float* src = xb + (size_t)cp * HW + pbase + sh;

    float v[16];
    #pragma unroll
    for (int j = 0; j < 8; j++) {
        int p = pbase + 2 * j;
        int wcol = p % 56;
        int ww = wcol + sh;
        bool ok = (p < HW) && (ww >= 0) && (ww < 56);
        float2 f = ok ? *(const float2*)(src + 2 * j) : make_float2(0.f, 0.f);
        v[2 * j] = f.x; v[2 * j + 1] = f.y;
    }
    uint2 hi[4], lo[4];
    #pragma unroll
    for (int q = 0; q < 4; q++) split4(v + 4 * q, hi[q], lo[q]);
    char* bh = Bsp + mrow * RSB + pq * 32;
    char* bl = Bsp + (32 + mrow) * RSB + pq * 32;
    *(uint4*)(bh)      = make_uint4(hi[0].x, hi[0].y, hi[1].x, hi[1].y);
    *(uint4*)(bh + 16) = make_uint4(hi[2].x, hi[2].y, hi[3].x, hi[3].y);
    *(uint4*)(bl)      = make_uint4(lo[0].x, lo[0].y, lo[1].x, lo[1].y);
    *(uint4*)(bl + 16) = make_uint4(lo[2].x, lo[2].y, lo[3].x, lo[3].y);
}

__global__ void __launch_bounds__(256, 2) gemm2_kernel(const float* __restrict__ x,
                                                       float* __restrict__ out) {
    extern __shared__ char smem_raw[];
    __shared__ int s_next;
    char* smp = (char*)(((uintptr_t)smem_raw + 1023) & ~(uintptr_t)1023);

    const int tid = threadIdx.x, lane = tid & 31, wid = tid >> 5;
    const int wr = wid >> 1, wc = wid & 1;
    const int NCH = 12;

    int tile = blockIdx.x;
    while (tile < G2_TILES) {
        const int n = tile / 25;
        const int p0 = (tile - n * 25) * 128;

        const float* xb = x + (size_t)n * C * HW;
        const __nv_bfloat16* t7h = g_t7hi + (size_t)n * C * K3;
        const __nv_bfloat16* t7l = g_t7lo + (size_t)n * C * K3;

        float acc[2][8][4] = {};

        cpA(smp, t7h, t7l, K3, 0, tid);
        CP_COMMIT();
        g2_stageB(smp + TILE_A, xb, p0, 0, tid);
        CP_WAIT0();
        __syncthreads();

        for (int ch = 0; ch < NCH; ch++) {
            char* cur = smp + (ch & 1) * STAGE2;
            bool more = ch + 1 < NCH;
            char* nxt = smp + ((ch + 1) & 1) * STAGE2;
            int mn = (ch + 1) * 32;
            if (more) { cpA(nxt, t7h, t7l, K3, mn, tid); CP_COMMIT(); }
            mma_g2(smem_u32(cur), smem_u32(cur + TILE_A), wr, wc, lane, acc);
            if (more) g2_stageB(nxt + TILE_A, xb, p0, mn, tid);
            CP_WAIT0();
            __syncthreads();
        }

        // epilogue: out = acc + x * t8[c%4]
        const float* t8b = g_t8 + (size_t)n * 4 * HW;
        float* outb = out + (size_t)n * C * HW;
        #pragma unroll
        for (int mi = 0; mi < 2; mi++) {
            #pragma unroll
            for (int ni = 0; ni < 8; ni++) {
                int c = wr * 32 + mi * 16 + (lane >> 2);
                int p = p0 + wc * 64 + ni * 8 + (lane & 3) * 2;
                if (p < HW) {
                    #pragma unroll
                    for (int h = 0; h < 2; h++) {
                        int cc = c + h * 8;
                        float2 xv  = *(const float2*)(xb  + (size_t)cc * HW + p);
                        float2 t8v = *(const float2*)(t8b + (size_t)(cc & 3) * HW + p);
                        float2 o = make_float2(acc[mi][ni][2 * h]     + xv.x * t8v.x,
                                               acc[mi][ni][2 * h + 1] + xv.y * t8v.y);
                        *(float2*)(outb + (size_t)cc * HW + p) = o;
                    }
                }
            }
        }
        __syncthreads();   // smem + s_next safe
        if (tid == 0) s_next = atomicAdd(&g_ticket, 1);
        __syncthreads();
        tile = s_next;
    }
}

// ---------------------------------------------------------------------------
extern "C" void kernel_launch(void* const* d_in, const int* in_sizes, int n_in,
                              void* d_out, int out_size) {
    const float* x      = (const float*)d_in[0];
    const float* p2w    = (const float*)d_in[1];
    const float* p5w    = (const float*)d_in[2];
    const float* conv_w = (const float*)d_in[3];
    float* out = (float*)d_out;

    cudaFuncSetAttribute(gemm1_kernel, cudaFuncAttributeMaxDynamicSharedMemorySize, SMEM1);
    cudaFuncSetAttribute(gemm2_kernel, cudaFuncAttributeMaxDynamicSharedMemorySize, SMEM2);

    prep_kernel<<<dim3(98, NB), 256>>>(x, p5w, conv_w);
    gemm1_kernel<<<dim3(3, NB, NSPLIT), 256, SMEM1>>>(x, p2w);
    t7sum_kernel<<<1536, 256>>>();
    gemm2_kernel<<<G2_GRID, 256, SMEM2>>>(x, out);
}

// round 14
// speedup vs baseline: 1.6061x; 1.6061x over previous
#include <cuda_runtime.h>
#include <cuda_bf16.h>
#include <cstdint>

#define NB 32
#define C 128
#define HW 3136
#define K3 384
#define NSPLIT 3
#define SPL ((size_t)NB * C * K3)

// A tiles: 128 rows x [hi 32 | lo 32] bf16 = 128B + 16 pad = 144B stride
#define RS 144
#define TILE_A (128 * RS)                     // 18432
// gemm2 B tile (transposed): 64 rows (hi 32 + lo 32) x 128 p-cols = 256B + 16 pad
#define RSB 272
#define TILE_B2 (64 * RSB)                    // 17408
#define STAGE1 (2 * TILE_A)
#define STAGE2 (TILE_A + TILE_B2)
#define SMEM1 (2 * STAGE1 + 1024)
#define SMEM2 (2 * STAGE2 + 1024)

#define G2_TILES 800                          // 32 batches x 25 p-tiles
#define G2_GRID 296                           // 148 SM x 2 CTAs, one wave

__device__ float g_t8[NB * 4 * HW];
__device__ float g_t7p[NSPLIT * NB * C * K3];
__device__ __nv_bfloat16 g_t6hi[(size_t)NB * C * HW];
__device__ __nv_bfloat16 g_t6lo[(size_t)NB * C * HW];
__device__ __nv_bfloat16 g_t7hi[(size_t)NB * C * K3];
__device__ __nv_bfloat16 g_t7lo[(size_t)NB * C * K3];

// ---------------- helpers ----------------
__device__ __forceinline__ uint32_t smem_u32(const void* p) {
    uint32_t a;
    asm("{ .reg .u64 t; cvta.to.shared.u64 t, %1; cvt.u32.u64 %0, t; }" : "=r"(a) : "l"(p));
    return a;
}
#define CP16(dst, src) \
    asm volatile("cp.async.cg.shared.global [%0], [%1], 16;" :: "r"(dst), "l"(src))
#define CP_COMMIT() asm volatile("cp.async.commit_group;" ::: "memory")
#define CP_WAIT0()  asm volatile("cp.async.wait_group 0;" ::: "memory")

__device__ __forceinline__ void ldsm4(uint32_t addr, uint32_t* r) {
    asm volatile("ldmatrix.sync.aligned.m8n8.x4.shared.b16 {%0,%1,%2,%3}, [%4];"
                 : "=r"(r[0]), "=r"(r[1]), "=r"(r[2]), "=r"(r[3]) : "r"(addr));
}
__device__ __forceinline__ void ldsm4t(uint32_t addr, uint32_t* r) {
    asm volatile("ldmatrix.sync.aligned.m8n8.x4.trans.shared.b16 {%0,%1,%2,%3}, [%4];"
                 : "=r"(r[0]), "=r"(r[1]), "=r"(r[2]), "=r"(r[3]) : "r"(addr));
}
__device__ __forceinline__ void mma16816(float* c, const uint32_t a[4],
                                         uint32_t b0, uint32_t b1) {
    asm volatile(
        "mma.sync.aligned.m16n8k16.row.col.f32.bf16.bf16.f32 "
        "{%0,%1,%2,%3}, {%4,%5,%6,%7}, {%8,%9}, {%0,%1,%2,%3};"
        : "+f"(c[0]), "+f"(c[1]), "+f"(c[2]), "+f"(c[3])
        : "r"(a[0]), "r"(a[1]), "r"(a[2]), "r"(a[3]), "r"(b0), "r"(b1));
}
__device__ __forceinline__ void split4(const float v[4], uint2& hi, uint2& lo) {
    __nv_bfloat16 h0 = __float2bfloat16(v[0]), h1 = __float2bfloat16(v[1]);
    __nv_bfloat16 h2 = __float2bfloat16(v[2]), h3 = __float2bfloat16(v[3]);
    __nv_bfloat16 l0 = __float2bfloat16(v[0] - __bfloat162float(h0));
    __nv_bfloat16 l1 = __float2bfloat16(v[1] - __bfloat162float(h1));
    __nv_bfloat16 l2 = __float2bfloat16(v[2] - __bfloat162float(h2));
    __nv_bfloat16 l3 = __float2bfloat16(v[3] - __bfloat162float(h3));
    hi.x = (uint32_t)__bfloat16_as_ushort(h0) | ((uint32_t)__bfloat16_as_ushort(h1) << 16);
    hi.y = (uint32_t)__bfloat16_as_ushort(h2) | ((uint32_t)__bfloat16_as_ushort(h3) << 16);
    lo.x = (uint32_t)__bfloat16_as_ushort(l0) | ((uint32_t)__bfloat16_as_ushort(l1) << 16);
    lo.y = (uint32_t)__bfloat16_as_ushort(l2) | ((uint32_t)__bfloat16_as_ushort(l3) << 16);
}

// cp.async one A tile: 128 rows x [hi 64B | lo 64B] from packed bf16 planes
__device__ __forceinline__ void cpA(char* Asp, const __nv_bfloat16* hi,
                                    const __nv_bfloat16* lo, size_t rstride,
                                    int col0, int tid) {
    #pragma unroll
    for (int it = 0; it < 2; it++) {
        int idx = tid + it * 256;
        int r = idx >> 2, s = idx & 3;
        CP16(smem_u32(Asp + r * RS + s * 16),
             hi + (size_t)r * rstride + col0 + s * 8);
    }
    #pragma unroll
    for (int it = 0; it < 2; it++) {
        int idx = tid + it * 256;
        int r = idx >> 2, s = idx & 3;
        CP16(smem_u32(Asp + r * RS + 64 + s * 16),
             lo + (size_t)r * rstride + col0 + s * 8);
    }
}

// 3 product passes over preloaded fragments
#define MMA_PASSES(acc, ah, al, bh, bl, ldA_lo)                         \
    do {                                                                \
        _Pragma("unroll")                                               \
        for (int mi = 0; mi < 2; mi++)                                  \
            _Pragma("unroll")                                           \
            for (int nq = 0; nq < 4; nq++) {                            \
                mma16816(acc[mi][nq * 2],     ah[mi], bh[nq][0], bh[nq][1]); \
                mma16816(acc[mi][nq * 2 + 1], ah[mi], bh[nq][2], bh[nq][3]); \
            }                                                           \
        _Pragma("unroll")                                               \
        for (int mi = 0; mi < 2; mi++)                                  \
            _Pragma("unroll")                                           \
            for (int nq = 0; nq < 4; nq++) {                            \
                mma16816(acc[mi][nq * 2],     ah[mi], bl[nq][0], bl[nq][1]); \
                mma16816(acc[mi][nq * 2 + 1], ah[mi], bl[nq][2], bl[nq][3]); \
            }                                                           \
        ldA_lo;                                                         \
        _Pragma("unroll")                                               \
        for (int mi = 0; mi < 2; mi++)                                  \
            _Pragma("unroll")                                           \
            for (int nq = 0; nq < 4; nq++) {                            \
                mma16816(acc[mi][nq * 2],     al[mi], bh[nq][0], bh[nq][1]); \
                mma16816(acc[mi][nq * 2 + 1], al[mi], bh[nq][2], bh[nq][3]); \
            }                                                           \
    } while (0)

__device__ __forceinline__ void mma_g1(uint32_t As, uint32_t Bs, int wr, int wc,
                                       int lane, float acc[2][8][4]) {
    const uint32_t a_row = (uint32_t)(wr * 32 + (lane & 15)) * RS + ((lane >> 4) << 4);
    const int brow = (lane & 7) + ((lane & 16) >> 1);
    const uint32_t b_k = (uint32_t)((lane & 8) << 1);
    #pragma unroll
    for (int ks = 0; ks < 2; ks++) {
        uint32_t k16 = ks * 32;
        uint32_t ah[2][4], al[2][4], bh[4][4], bl[4][4];
        #pragma unroll
        for (int mi = 0; mi < 2; mi++)
            ldsm4(As + a_row + (uint32_t)(mi * 16) * RS + k16, ah[mi]);
        #pragma unroll
        for (int nq = 0; nq < 4; nq++) {
            uint32_t bbase = Bs + (uint32_t)(wc * 64 + nq * 16 + brow) * RS + k16 + b_k;
            ldsm4(bbase,      bh[nq]);
            ldsm4(bbase + 64, bl[nq]);
        }
        MMA_PASSES(acc, ah, al, bh, bl,
            { _Pragma("unroll")
              for (int mi = 0; mi < 2; mi++)
                  ldsm4(As + a_row + (uint32_t)(mi * 16) * RS + k16 + 64, al[mi]); });
    }
}

__device__ __forceinline__ void mma_g2(uint32_t As, uint32_t Bs, int wr, int wc,
                                       int lane, float acc[2][8][4]) {
    const uint32_t a_row = (uint32_t)(wr * 32 + (lane & 15)) * RS + ((lane >> 4) << 4);
    const uint32_t b_row = (uint32_t)((lane & 7) + (lane & 8));
    const uint32_t b_pofs = (uint32_t)((lane & 16));
    #pragma unroll
    for (int ks = 0; ks < 2; ks++) {
        uint32_t k16 = ks * 32;
        uint32_t mb = ks * 16;
        uint32_t ah[2][4], al[2][4], bh[4][4], bl[4][4];
        #pragma unroll
        for (int mi = 0; mi < 2; mi++)
            ldsm4(As + a_row + (uint32_t)(mi * 16) * RS + k16, ah[mi]);
        #pragma unroll
        for (int nq = 0; nq < 4; nq++) {
            uint32_t addr = Bs + (mb + b_row) * RSB
                          + (uint32_t)(wc * 64 + nq * 16) * 2 + b_pofs;
            ldsm4t(addr,            bh[nq]);
            ldsm4t(addr + 32 * RSB, bl[nq]);
        }
        MMA_PASSES(acc, ah, al, bh, bl,
            { _Pragma("unroll")
              for (int mi = 0; mi < 2; mi++)
                  ldsm4(As + a_row + (uint32_t)(mi * 16) * RS + k16 + 64, al[mi]); });
    }
}

// ---------------------------------------------------------------------------
// prep: t8 reduction + packed t6 hi/lo planes. grid (98, 32) x 256
// ---------------------------------------------------------------------------
__global__ void __launch_bounds__(256) prep_kernel(const float* __restrict__ x,
                                                   const float* __restrict__ p5w,
                                                   const float* __restrict__ conv_w) {
    __shared__ float red[8][4][32];
    int n = blockIdx.y;
    int tid = threadIdx.x;
    int pl = tid & 31, q = tid >> 5;
    int p = blockIdx.x * 32 + pl;
    int rp = (p >= 56) ? (p - 56) : (p + 3080);

    const float* xb = x + (size_t)n * C * HW;
    __nv_bfloat16* t6h = g_t6hi + (size_t)n * C * HW;
    __nv_bfloat16* t6l = g_t6lo + (size_t)n * C * HW;

    float s0 = 0.f, s1 = 0.f, s2 = 0.f, s3 = 0.f;
    int c0 = q * 16;
    #pragma unroll 4
    for (int i = 0; i < 16; i++) {
        int c = c0 + i;
        float xp = xb[(size_t)c * HW + p];
        float xr = xb[(size_t)c * HW + rp];
        float v = xp + xr;
        __nv_bfloat16 h = __float2bfloat16(v);
        t6h[(size_t)c * HW + p] = h;
        t6l[(size_t)c * HW + p] = __float2bfloat16(v - __bfloat162float(h));
        float t = __ldg(&p5w[c]) * xr;
        s0 = fmaf(__ldg(&conv_w[c]),       t, s0);
        s1 = fmaf(__ldg(&conv_w[128 + c]), t, s1);
        s2 = fmaf(__ldg(&conv_w[256 + c]), t, s2);
        s3 = fmaf(__ldg(&conv_w[384 + c]), t, s3);
    }
    red[q][0][pl] = s0; red[q][1][pl] = s1; red[q][2][pl] = s2; red[q][3][pl] = s3;
    __syncthreads();
    if (tid < 128) {
        int j = tid >> 5, pl2 = tid & 31;
        float r = 0.f;
        #pragma unroll
        for (int qq = 0; qq < 8; qq++) r += red[qq][j][pl2];
        g_t8[((size_t)n * 4 + j) * HW + blockIdx.x * 32 + pl2] = r;
    }
}

// ---------------------------------------------------------------------------
// gemm1: D rows = c' (A = t6 planes via cp.async), cols = m. K chunks of 32.
// grid (3, 32, 3) x 256, occ 2   [R12 champion version, unchanged]
// ---------------------------------------------------------------------------
__device__ __forceinline__ void g1_stageB(char* Bsp, const float* xb,
                                          const float* p2w, int m0, int p0, int tid) {
    int col4 = (tid & 7) * 4;
    int rbase = tid >> 3;
    #pragma unroll
    for (int pass = 0; pass < 4; pass++) {
        int mr = rbase + pass * 32;
        int m = m0 + mr, c = m / 3, k = m - 3 * c, sh = 2 * k - 2;
        float4 w4 = *reinterpret_cast<const float4*>(p2w + (size_t)m * HW + p0 + col4);
        int p = p0 + col4;
        int hh = p / 56 + sh;
        float v[4] = {0.f, 0.f, 0.f, 0.f};
        if (hh >= 0 && hh < 56) {
            float4 x4 = *reinterpret_cast<const float4*>(
                xb + (size_t)c * HW + p + sh * 56);
            v[0] = w4.x * x4.x; v[1] = w4.y * x4.y;
            v[2] = w4.z * x4.z; v[3] = w4.w * x4.w;
        }
        uint2 hi, lo; split4(v, hi, lo);
        char* bb = Bsp + mr * RS + col4 * 2;
        *(uint2*)(bb)      = hi;
        *(uint2*)(bb + 64) = lo;
    }
}

__global__ void __launch_bounds__(256, 2) gemm1_kernel(const float* __restrict__ x,
                                                       const float* __restrict__ p2w) {
    extern __shared__ char smem_raw[];
    char* smp = (char*)(((uintptr_t)smem_raw + 1023) & ~(uintptr_t)1023);

    const int tid = threadIdx.x, lane = tid & 31, wid = tid >> 5;
    const int wr = wid >> 1, wc = wid & 1;
    const int n = blockIdx.y, m0 = blockIdx.x * 128, s = blockIdx.z;

    const float* xb = x + (size_t)n * C * HW;
    const __nv_bfloat16* t6h = g_t6hi + (size_t)n * C * HW;
    const __nv_bfloat16* t6l = g_t6lo + (size_t)n * C * HW;

    float acc[2][8][4] = {};
    const int beg[4] = {0, 33, 66, 98};
    const int nch = beg[s + 1] - beg[s];
    const int pbase = beg[s] * 32;

    cpA(smp, t6h, t6l, HW, pbase, tid);
    CP_COMMIT();
    g1_stageB(smp + TILE_A, xb, p2w, m0, pbase, tid);
    CP_WAIT0();
    __syncthreads();

    for (int ch = 0; ch < nch; ch++) {
        char* cur = smp + (ch & 1) * STAGE1;
        bool more = ch + 1 < nch;
        char* nxt = smp + ((ch + 1) & 1) * STAGE1;
        int pn = pbase + (ch + 1) * 32;
        if (more) { cpA(nxt, t6h, t6l, HW, pn, tid); CP_COMMIT(); }
        mma_g1(smem_u32(cur), smem_u32(cur + TILE_A), wr, wc, lane, acc);
        if (more) g1_stageB(nxt + TILE_A, xb, p2w, m0, pn, tid);
        CP_WAIT0();
        __syncthreads();
    }

    const float SC = 9.1126371e-4f;   // 1/(sqrt(3136)*sqrt(384))
    float* ob = g_t7p + ((size_t)(s * NB + n)) * C * K3;
    #pragma unroll
    for (int mi = 0; mi < 2; mi++) {
        #pragma unroll
        for (int ni = 0; ni < 8; ni++) {
            int row = wr * 32 + mi * 16 + (lane >> 2);
            int col = m0 + wc * 64 + ni * 8 + (lane & 3) * 2;
            *(float2*)(ob + (size_t)row * K3 + col) =
                make_float2(acc[mi][ni][0] * SC, acc[mi][ni][1] * SC);
            *(float2*)(ob + (size_t)(row + 8) * K3 + col) =
                make_float2(acc[mi][ni][2] * SC, acc[mi][ni][3] * SC);
        }
    }
}

// ---------------------------------------------------------------------------
// t7sum: sum 3 partials, pack to hi/lo planes. grid 1536 x 256
// ---------------------------------------------------------------------------
__global__ void __launch_bounds__(256) t7sum_kernel() {
    size_t i = ((size_t)blockIdx.x * 256 + threadIdx.x) * 4;
    float4 v0 = *(const float4*)(g_t7p + i);
    float4 v1 = *(const float4*)(g_t7p + SPL + i);
    float4 v2 = *(const float4*)(g_t7p + 2 * SPL + i);
    float v[4] = {v0.x + v1.x + v2.x, v0.y + v1.y + v2.y,
                  v0.z + v1.z + v2.z, v0.w + v1.w + v2.w};
    uint2 hi, lo; split4(v, hi, lo);
    *(uint2*)(g_t7hi + i) = hi;
    *(uint2*)(g_t7lo + i) = lo;
}

// ---------------------------------------------------------------------------
// gemm2: persistent grid 296, static stride, cross-tile prologue pipelining.
// ---------------------------------------------------------------------------
__device__ __forceinline__ void g2_stageB(char* Bsp, const float* xb,
                                          int p0, int m0c, int tid) {
    int mrow = tid & 31;
    int pq = tid >> 5;
    int m = m0c + mrow, cp = m / 3, k = m - 3 * cp, sh = 2 * k - 2;
    int pbase = p0 + pq * 16;
    const float* src = xb + (size_t)cp * HW + pbase + sh;

    float v[16];
    #pragma unroll
    for (int j = 0; j < 8; j++) {
        int p = pbase + 2 * j;
        int wcol = p % 56;
        int ww = wcol + sh;
        bool ok = (p < HW) && (ww >= 0) && (ww < 56);
        float2 f = ok ? *(const float2*)(src + 2 * j) : make_float2(0.f, 0.f);
        v[2 * j] = f.x; v[2 * j + 1] = f.y;
    }
    uint2 hi[4], lo[4];
    #pragma unroll
    for (int q = 0; q < 4; q++) split4(v + 4 * q, hi[q], lo[q]);
    char* bh = Bsp + mrow * RSB + pq * 32;
    char* bl = Bsp + (32 + mrow) * RSB + pq * 32;
    *(uint4*)(bh)      = make_uint4(hi[0].x, hi[0].y, hi[1].x, hi[1].y);
    *(uint4*)(bh + 16) = make_uint4(hi[2].x, hi[2].y, hi[3].x, hi[3].y);
    *(uint4*)(bl)      = make_uint4(lo[0].x, lo[0].y, lo[1].x, lo[1].y);
    *(uint4*)(bl + 16) = make_uint4(lo[2].x, lo[2].y, lo[3].x, lo[3].y);
}

__global__ void __launch_bounds__(256, 2) gemm2_kernel(const float* __restrict__ x,
                                                       float* __restrict__ out) {
    extern __shared__ char smem_raw[];
    char* smp = (char*)(((uintptr_t)smem_raw + 1023) & ~(uintptr_t)1023);

    const int tid = threadIdx.x, lane = tid & 31, wid = tid >> 5;
    const int wr = wid >> 1, wc = wid & 1;
    const int NCH = 12;

    int tile = blockIdx.x;
    if (tile >= G2_TILES) return;

    // prologue for first tile
    {
        int n = tile / 25, p0 = (tile - n * 25) * 128;
        const float* xb = x + (size_t)n * C * HW;
        cpA(smp, g_t7hi + (size_t)n * C * K3, g_t7lo + (size_t)n * C * K3,
            K3, 0, tid);
        CP_COMMIT();
        g2_stageB(smp + TILE_A, xb, p0, 0, tid);
        CP_WAIT0();
        __syncthreads();
    }

    while (tile < G2_TILES) {
        const int n = tile / 25;
        const int p0 = (tile - n * 25) * 128;
        const int tn = tile + G2_GRID;
        const float* xb = x + (size_t)n * C * HW;
        const __nv_bfloat16* t7h = g_t7hi + (size_t)n * C * K3;
        const __nv_bfloat16* t7l = g_t7lo + (size_t)n * C * K3;

        float acc[2][8][4] = {};

        for (int ch = 0; ch < NCH; ch++) {
            char* cur = smp + (ch & 1) * STAGE2;
            char* nxt = smp + ((ch + 1) & 1) * STAGE2;
            bool more = ch + 1 < NCH;
            bool pre  = (!more) && (tn < G2_TILES);
            if (more) {
                int mn = (ch + 1) * 32;
                cpA(nxt, t7h, t7l, K3, mn, tid);
                CP_COMMIT();
                mma_g2(smem_u32(cur), smem_u32(cur + TILE_A), wr, wc, lane, acc);
                g2_stageB(nxt + TILE_A, xb, p0, mn, tid);
            } else if (pre) {
                // stage NEXT tile's chunk 0 into buf0 ((ch+1)&1 == 0)
                int n2 = tn / 25, p02 = (tn - n2 * 25) * 128;
                const float* xb2 = x + (size_t)n2 * C * HW;
                cpA(nxt, g_t7hi + (size_t)n2 * C * K3,
                    g_t7lo + (size_t)n2 * C * K3, K3, 0, tid);
                CP_COMMIT();
                mma_g2(smem_u32(cur), smem_u32(cur + TILE_A), wr, wc, lane, acc);
                g2_stageB(nxt + TILE_A, xb2, p02, 0, tid);
            } else {
                mma_g2(smem_u32(cur), smem_u32(cur + TILE_A), wr, wc, lane, acc);
            }
            CP_WAIT0();
            __syncthreads();
        }

        // epilogue: out = acc + x * t8[c%4]   (no smem use; buf0 holds next tile)
        const float* t8b = g_t8 + (size_t)n * 4 * HW;
        float* outb = out + (size_t)n * C * HW;
        #pragma unroll
        for (int mi = 0; mi < 2; mi++) {
            #pragma unroll
            for (int ni = 0; ni < 8; ni++) {
                int c = wr * 32 + mi * 16 + (lane >> 2);
                int p = p0 + wc * 64 + ni * 8 + (lane & 3) * 2;
                if (p < HW) {
                    #pragma unroll
                    for (int h = 0; h < 2; h++) {
                        int cc = c + h * 8;
                        float2 xv  = *(const float2*)(xb  + (size_t)cc * HW + p);
                        float2 t8v = *(const float2*)(t8b + (size_t)(cc & 3) * HW + p);
                        float2 o = make_float2(acc[mi][ni][2 * h]     + xv.x * t8v.x,
                                               acc[mi][ni][2 * h + 1] + xv.y * t8v.y);
                        *(float2*)(outb + (size_t)cc * HW + p) = o;
                    }
                }
            }
        }
        tile = tn;
    }
}

// ---------------------------------------------------------------------------
extern "C" void kernel_launch(void* const* d_in, const int* in_sizes, int n_in,
                              void* d_out, int out_size) {
    const float* x      = (const float*)d_in[0];
    const float* p2w    = (const float*)d_in[1];
    const float* p5w    = (const float*)d_in[2];
    const float* conv_w = (const float*)d_in[3];
    float* out = (float*)d_out;

    cudaFuncSetAttribute(gemm1_kernel, cudaFuncAttributeMaxDynamicSharedMemorySize, SMEM1);
    cudaFuncSetAttribute(gemm2_kernel, cudaFuncAttributeMaxDynamicSharedMemorySize, SMEM2);

    prep_kernel<<<dim3(98, NB), 256>>>(x, p5w, conv_w);
    gemm1_kernel<<<dim3(3, NB, NSPLIT), 256, SMEM1>>>(x, p2w);
    t7sum_kernel<<<1536, 256>>>();
    gemm2_kernel<<<G2_GRID, 256, SMEM2>>>(x, out);
}

// round 15
// speedup vs baseline: 1.9357x; 1.2052x over previous
#include <cuda_runtime.h>
#include <cuda_fp16.h>
#include <cstdint>

#define NB 32
#define C 128
#define HW 3136
#define K3 384
#define NSPLIT 3
#define SPL ((size_t)NB * C * K3)

// A tiles: 128 rows x [hi 32 | lo 32] fp16 = 128B + 16 pad = 144B stride
#define RS 144
#define TILE_A (128 * RS)                     // 18432
// gemm1 B tile: 128 rows(m) x 32 fp16 k-cols = 64B + 16 pad = 80B stride
#define RSB1 80
#define TILE_B1 (128 * RSB1)                  // 10240
// gemm2 B tile (transposed, hi only): 32 rows(m) x 128 p fp16 = 256B + 16 pad
#define RSB 272
#define TILE_B2 (32 * RSB)                    // 8704
#define STAGE1 (TILE_A + TILE_B1)             // 28672
#define STAGE2 (TILE_A + TILE_B2)             // 27136
#define SMEM1 (2 * STAGE1 + 1024)             // 58368
#define SMEM2 (2 * STAGE2 + 1024)             // 55296

#define G2_TILES 800
#define G2_GRID 592

__device__ float g_t8[NB * 4 * HW];
__device__ float g_t7p[NSPLIT * NB * C * K3];
__device__ __half g_t6hi[(size_t)NB * C * HW];
__device__ __half g_t6lo[(size_t)NB * C * HW];
__device__ __half g_t7hi[(size_t)NB * C * K3];
__device__ __half g_t7lo[(size_t)NB * C * K3];

// ---------------- helpers ----------------
__device__ __forceinline__ uint32_t smem_u32(const void* p) {
    uint32_t a;
    asm("{ .reg .u64 t; cvta.to.shared.u64 t, %1; cvt.u32.u64 %0, t; }" : "=r"(a) : "l"(p));
    return a;
}
#define CP16(dst, src) \
    asm volatile("cp.async.cg.shared.global [%0], [%1], 16;" :: "r"(dst), "l"(src))
#define CP_COMMIT() asm volatile("cp.async.commit_group;" ::: "memory")
#define CP_WAIT0()  asm volatile("cp.async.wait_group 0;" ::: "memory")

__device__ __forceinline__ void ldsm4(uint32_t addr, uint32_t* r) {
    asm volatile("ldmatrix.sync.aligned.m8n8.x4.shared.b16 {%0,%1,%2,%3}, [%4];"
                 : "=r"(r[0]), "=r"(r[1]), "=r"(r[2]), "=r"(r[3]) : "r"(addr));
}
__device__ __forceinline__ void ldsm4t(uint32_t addr, uint32_t* r) {
    asm volatile("ldmatrix.sync.aligned.m8n8.x4.trans.shared.b16 {%0,%1,%2,%3}, [%4];"
                 : "=r"(r[0]), "=r"(r[1]), "=r"(r[2]), "=r"(r[3]) : "r"(addr));
}
__device__ __forceinline__ void mma16816(float* c, const uint32_t a[4],
                                         uint32_t b0, uint32_t b1) {
    asm volatile(
        "mma.sync.aligned.m16n8k16.row.col.f32.f16.f16.f32 "
        "{%0,%1,%2,%3}, {%4,%5,%6,%7}, {%8,%9}, {%0,%1,%2,%3};"
        : "+f"(c[0]), "+f"(c[1]), "+f"(c[2]), "+f"(c[3])
        : "r"(a[0]), "r"(a[1]), "r"(a[2]), "r"(a[3]), "r"(b0), "r"(b1));
}
// fp16 hi/lo split of 4 floats
__device__ __forceinline__ void split4h(const float v[4], uint2& hi, uint2& lo) {
    __half h0 = __float2half(v[0]), h1 = __float2half(v[1]);
    __half h2 = __float2half(v[2]), h3 = __float2half(v[3]);
    __half l0 = __float2half(v[0] - __half2float(h0));
    __half l1 = __float2half(v[1] - __half2float(h1));
    __half l2 = __float2half(v[2] - __half2float(h2));
    __half l3 = __float2half(v[3] - __half2float(h3));
    hi.x = (uint32_t)__half_as_ushort(h0) | ((uint32_t)__half_as_ushort(h1) << 16);
    hi.y = (uint32_t)__half_as_ushort(h2) | ((uint32_t)__half_as_ushort(h3) << 16);
    lo.x = (uint32_t)__half_as_ushort(l0) | ((uint32_t)__half_as_ushort(l1) << 16);
    lo.y = (uint32_t)__half_as_ushort(l2) | ((uint32_t)__half_as_ushort(l3) << 16);
}
// fp16 single-precision pack of 4 floats
__device__ __forceinline__ uint2 pack4h(const float v[4]) {
    __half h0 = __float2half(v[0]), h1 = __float2half(v[1]);
    __half h2 = __float2half(v[2]), h3 = __float2half(v[3]);
    uint2 r;
    r.x = (uint32_t)__half_as_ushort(h0) | ((uint32_t)__half_as_ushort(h1) << 16);
    r.y = (uint32_t)__half_as_ushort(h2) | ((uint32_t)__half_as_ushort(h3) << 16);
    return r;
}

// cp.async one A tile: 128 rows x [hi 64B | lo 64B] from packed fp16 planes
__device__ __forceinline__ void cpA(char* Asp, const __half* hi,
                                    const __half* lo, size_t rstride,
                                    int col0, int tid) {
    #pragma unroll
    for (int it = 0; it < 2; it++) {
        int idx = tid + it * 256;
        int r = idx >> 2, s = idx & 3;
        CP16(smem_u32(Asp + r * RS + s * 16),
             hi + (size_t)r * rstride + col0 + s * 8);
    }
    #pragma unroll
    for (int it = 0; it < 2; it++) {
        int idx = tid + it * 256;
        int r = idx >> 2, s = idx & 3;
        CP16(smem_u32(Asp + r * RS + 64 + s * 16),
             lo + (size_t)r * rstride + col0 + s * 8);
    }
}

// 2 product passes: Ah*Bh then Al*Bh
#define MMA_PASSES2(acc, ah, al, bh)                                    \
    do {                                                                \
        _Pragma("unroll")                                               \
        for (int mi = 0; mi < 2; mi++)                                  \
            _Pragma("unroll")                                           \
            for (int nq = 0; nq < 4; nq++) {                            \
                mma16816(acc[mi][nq * 2],     ah[mi], bh[nq][0], bh[nq][1]); \
                mma16816(acc[mi][nq * 2 + 1], ah[mi], bh[nq][2], bh[nq][3]); \
            }                                                           \
        _Pragma("unroll")                                               \
        for (int mi = 0; mi < 2; mi++)                                  \
            _Pragma("unroll")                                           \
            for (int nq = 0; nq < 4; nq++) {                            \
                mma16816(acc[mi][nq * 2],     al[mi], bh[nq][0], bh[nq][1]); \
                mma16816(acc[mi][nq * 2 + 1], al[mi], bh[nq][2], bh[nq][3]); \
            }                                                           \
    } while (0)

__device__ __forceinline__ void mma_g1(uint32_t As, uint32_t Bs, int wr, int wc,
                                       int lane, float acc[2][8][4]) {
    const uint32_t a_row = (uint32_t)(wr * 32 + (lane & 15)) * RS + ((lane >> 4) << 4);
    const int brow = (lane & 7) + ((lane & 16) >> 1);
    const uint32_t b_k = (uint32_t)((lane & 8) << 1);
    #pragma unroll
    for (int ks = 0; ks < 2; ks++) {
        uint32_t k16 = ks * 32;
        uint32_t ah[2][4], al[2][4], bh[4][4];
        #pragma unroll
        for (int mi = 0; mi < 2; mi++) {
            uint32_t base = As + a_row + (uint32_t)(mi * 16) * RS + k16;
            ldsm4(base,      ah[mi]);
            ldsm4(base + 64, al[mi]);
        }
        #pragma unroll
        for (int nq = 0; nq < 4; nq++)
            ldsm4(Bs + (uint32_t)(wc * 64 + nq * 16 + brow) * RSB1 + k16 + b_k,
                  bh[nq]);
        MMA_PASSES2(acc, ah, al, bh);
    }
}

__device__ __forceinline__ void mma_g2(uint32_t As, uint32_t Bs, int wr, int wc,
                                       int lane, float acc[2][8][4]) {
    const uint32_t a_row = (uint32_t)(wr * 32 + (lane & 15)) * RS + ((lane >> 4) << 4);
    const uint32_t b_row = (uint32_t)((lane & 7) + (lane & 8));
    const uint32_t b_pofs = (uint32_t)((lane & 16));
    #pragma unroll
    for (int ks = 0; ks < 2; ks++) {
        uint32_t k16 = ks * 32;
        uint32_t mb = ks * 16;
        uint32_t ah[2][4], al[2][4], bh[4][4];
        #pragma unroll
        for (int mi = 0; mi < 2; mi++) {
            uint32_t base = As + a_row + (uint32_t)(mi * 16) * RS + k16;
            ldsm4(base,      ah[mi]);
            ldsm4(base + 64, al[mi]);
        }
        #pragma unroll
        for (int nq = 0; nq < 4; nq++)
            ldsm4t(Bs + (mb + b_row) * RSB
                   + (uint32_t)(wc * 64 + nq * 16) * 2 + b_pofs, bh[nq]);
        MMA_PASSES2(acc, ah, al, bh);
    }
}

// ---------------------------------------------------------------------------
// prep: t8 reduction + packed t6 fp16 hi/lo planes. grid (98, 32) x 256
// ---------------------------------------------------------------------------
__global__ void __launch_bounds__(256) prep_kernel(const float* __restrict__ x,
                                                   const float* __restrict__ p5w,
                                                   const float* __restrict__ conv_w) {
    __shared__ float red[8][4][32];
    int n = blockIdx.y;
    int tid = threadIdx.x;
    int pl = tid & 31, q = tid >> 5;
    int p = blockIdx.x * 32 + pl;
    int rp = (p >= 56) ? (p - 56) : (p + 3080);

    const float* xb = x + (size_t)n * C * HW;
    __half* t6h = g_t6hi + (size_t)n * C * HW;
    __half* t6l = g_t6lo + (size_t)n * C * HW;

    float s0 = 0.f, s1 = 0.f, s2 = 0.f, s3 = 0.f;
    int c0 = q * 16;
    #pragma unroll 4
    for (int i = 0; i < 16; i++) {
        int c = c0 + i;
        float xp = xb[(size_t)c * HW + p];
        float xr = xb[(size_t)c * HW + rp];
        float v = xp + xr;
        __half h = __float2half(v);
        t6h[(size_t)c * HW + p] = h;
        t6l[(size_t)c * HW + p] = __float2half(v - __half2float(h));
        float t = __ldg(&p5w[c]) * xr;
        s0 = fmaf(__ldg(&conv_w[c]),       t, s0);
        s1 = fmaf(__ldg(&conv_w[128 + c]), t, s1);
        s2 = fmaf(__ldg(&conv_w[256 + c]), t, s2);
        s3 = fmaf(__ldg(&conv_w[384 + c]), t, s3);
    }
    red[q][0][pl] = s0; red[q][1][pl] = s1; red[q][2][pl] = s2; red[q][3][pl] = s3;
    __syncthreads();
    if (tid < 128) {
        int j = tid >> 5, pl2 = tid & 31;
        float r = 0.f;
        #pragma unroll
        for (int qq = 0; qq < 8; qq++) r += red[qq][j][pl2];
        g_t8[((size_t)n * 4 + j) * HW + blockIdx.x * 32 + pl2] = r;
    }
}

// ---------------------------------------------------------------------------
// gemm1: D rows = c' (A = t6 planes via cp.async), cols = m. K chunks of 32.
// B = p2w*unfold_h(x) rounded to single fp16. Stores UNSCALED t7 partials.
// grid (3, 32, 3) x 256, occ 2
// ---------------------------------------------------------------------------
__device__ __forceinline__ void g1_stageB(char* Bsp, const float* xb,
                                          const float* p2w, int m0, int p0, int tid) {
    int col4 = (tid & 7) * 4;
    int rbase = tid >> 3;
    #pragma unroll
    for (int pass = 0; pass < 4; pass++) {
        int mr = rbase + pass * 32;
        int m = m0 + mr, c = m / 3, k = m - 3 * c, sh = 2 * k - 2;
        float4 w4 = *reinterpret_cast<const float4*>(p2w + (size_t)m * HW + p0 + col4);
        int p = p0 + col4;
        int hh = p / 56 + sh;
        float v[4] = {0.f, 0.f, 0.f, 0.f};
        if (hh >= 0 && hh < 56) {
            float4 x4 = *reinterpret_cast<const float4*>(
                xb + (size_t)c * HW + p + sh * 56);
            v[0] = w4.x * x4.x; v[1] = w4.y * x4.y;
            v[2] = w4.z * x4.z; v[3] = w4.w * x4.w;
        }
        *(uint2*)(Bsp + mr * RSB1 + col4 * 2) = pack4h(v);
    }
}

__global__ void __launch_bounds__(256, 2) gemm1_kernel(const float* __restrict__ x,
                                                       const float* __restrict__ p2w) {
    extern __shared__ char smem_raw[];
    char* smp = (char*)(((uintptr_t)smem_raw + 1023) & ~(uintptr_t)1023);

    const int tid = threadIdx.x, lane = tid & 31, wid = tid >> 5;
    const int wr = wid >> 1, wc = wid & 1;
    const int n = blockIdx.y, m0 = blockIdx.x * 128, s = blockIdx.z;

    const float* xb = x + (size_t)n * C * HW;
    const __half* t6h = g_t6hi + (size_t)n * C * HW;
    const __half* t6l = g_t6lo + (size_t)n * C * HW;

    float acc[2][8][4] = {};
    const int beg[4] = {0, 33, 66, 98};
    const int nch = beg[s + 1] - beg[s];
    const int pbase = beg[s] * 32;

    cpA(smp, t6h, t6l, HW, pbase, tid);
    CP_COMMIT();
    g1_stageB(smp + TILE_A, xb, p2w, m0, pbase, tid);
    CP_WAIT0();
    __syncthreads();

    for (int ch = 0; ch < nch; ch++) {
        char* cur = smp + (ch & 1) * STAGE1;
        bool more = ch + 1 < nch;
        char* nxt = smp + ((ch + 1) & 1) * STAGE1;
        int pn = pbase + (ch + 1) * 32;
        if (more) { cpA(nxt, t6h, t6l, HW, pn, tid); CP_COMMIT(); }
        mma_g1(smem_u32(cur), smem_u32(cur + TILE_A), wr, wc, lane, acc);
        if (more) g1_stageB(nxt + TILE_A, xb, p2w, m0, pn, tid);
        CP_WAIT0();
        __syncthreads();
    }

    // store UNSCALED partials (scale applied in gemm2 epilogue)
    float* ob = g_t7p + ((size_t)(s * NB + n)) * C * K3;
    #pragma unroll
    for (int mi = 0; mi < 2; mi++) {
        #pragma unroll
        for (int ni = 0; ni < 8; ni++) {
            int row = wr * 32 + mi * 16 + (lane >> 2);
            int col = m0 + wc * 64 + ni * 8 + (lane & 3) * 2;
            *(float2*)(ob + (size_t)row * K3 + col) =
                make_float2(acc[mi][ni][0], acc[mi][ni][1]);
            *(float2*)(ob + (size_t)(row + 8) * K3 + col) =
                make_float2(acc[mi][ni][2], acc[mi][ni][3]);
        }
    }
}

// ---------------------------------------------------------------------------
// t7sum: sum 3 partials, pack to fp16 hi/lo planes (unscaled). grid 1536
// ---------------------------------------------------------------------------
__global__ void __launch_bounds__(256) t7sum_kernel() {
    size_t i = ((size_t)blockIdx.x * 256 + threadIdx.x) * 4;
    float4 v0 = *(const float4*)(g_t7p + i);
    float4 v1 = *(const float4*)(g_t7p + SPL + i);
    float4 v2 = *(const float4*)(g_t7p + 2 * SPL + i);
    float v[4] = {v0.x + v1.x + v2.x, v0.y + v1.y + v2.y,
                  v0.z + v1.z + v2.z, v0.w + v1.w + v2.w};
    uint2 hi, lo; split4h(v, hi, lo);
    *(uint2*)(g_t7hi + i) = hi;
    *(uint2*)(g_t7lo + i) = lo;
}

// ---------------------------------------------------------------------------
// gemm2: persistent grid 592, static stride (R12 champion scheduling).
// D rows = c (A = t7 planes via cp.async), cols = p. B = unfold_w(x) fp16.
// Epilogue applies SC and fuses t9.
// ---------------------------------------------------------------------------
__device__ __forceinline__ void g2_stageB(char* Bsp, const float* xb,
                                          int p0, int m0c, int tid) {
    int mrow = tid & 31;
    int pq = tid >> 5;
    int m = m0c + mrow, cp = m / 3, k = m - 3 * cp, sh = 2 * k - 2;
    int pbase = p0 + pq * 16;
    const float* src = xb + (size_t)cp * HW + pbase + sh;

    float v[16];
    #pragma unroll
    for (int j = 0; j < 8; j++) {
        int p = pbase + 2 * j;
        int wcol = p % 56;
        int ww = wcol + sh;
        bool ok = (p < HW) && (ww >= 0) && (ww < 56);
        float2 f = ok ? *(const float2*)(src + 2 * j) : make_float2(0.f, 0.f);
        v[2 * j] = f.x; v[2 * j + 1] = f.y;
    }
    uint2 h0 = pack4h(v), h1 = pack4h(v + 4), h2 = pack4h(v + 8), h3 = pack4h(v + 12);
    char* bh = Bsp + mrow * RSB + pq * 32;
    *(uint4*)(bh)      = make_uint4(h0.x, h0.y, h1.x, h1.y);
    *(uint4*)(bh + 16) = make_uint4(h2.x, h2.y, h3.x, h3.y);
}

__global__ void __launch_bounds__(256, 2) gemm2_kernel(const float* __restrict__ x,
                                                       float* __restrict__ out) {
    extern __shared__ char smem_raw[];
    char* smp = (char*)(((uintptr_t)smem_raw + 1023) & ~(uintptr_t)1023);

    const int tid = threadIdx.x, lane = tid & 31, wid = tid >> 5;
    const int wr = wid >> 1, wc = wid & 1;
    const int NCH = 12;
    const float SC = 9.1126371e-4f;   // 1/(sqrt(3136)*sqrt(384))

    for (int tile = blockIdx.x; tile < G2_TILES; tile += G2_GRID) {
        const int n = tile / 25;
        const int p0 = (tile - n * 25) * 128;

        const float* xb = x + (size_t)n * C * HW;
        const __half* t7h = g_t7hi + (size_t)n * C * K3;
        const __half* t7l = g_t7lo + (size_t)n * C * K3;

        float acc[2][8][4] = {};

        cpA(smp, t7h, t7l, K3, 0, tid);
        CP_COMMIT();
        g2_stageB(smp + TILE_A, xb, p0, 0, tid);
        CP_WAIT0();
        __syncthreads();

        for (int ch = 0; ch < NCH; ch++) {
            char* cur = smp + (ch & 1) * STAGE2;
            bool more = ch + 1 < NCH;
            char* nxt = smp + ((ch + 1) & 1) * STAGE2;
            int mn = (ch + 1) * 32;
            if (more) { cpA(nxt, t7h, t7l, K3, mn, tid); CP_COMMIT(); }
            mma_g2(smem_u32(cur), smem_u32(cur + TILE_A), wr, wc, lane, acc);
            if (more) g2_stageB(nxt + TILE_A, xb, p0, mn, tid);
            CP_WAIT0();
            __syncthreads();
        }

        // epilogue: out = SC*acc + x * t8[c%4]
        const float* t8b = g_t8 + (size_t)n * 4 * HW;
        float* outb = out + (size_t)n * C * HW;
        #pragma unroll
        for (int mi = 0; mi < 2; mi++) {
            #pragma unroll
            for (int ni = 0; ni < 8; ni++) {
                int c = wr * 32 + mi * 16 + (lane >> 2);
                int p = p0 + wc * 64 + ni * 8 + (lane & 3) * 2;
                if (p < HW) {
                    #pragma unroll
                    for (int h = 0; h < 2; h++) {
                        int cc = c + h * 8;
                        float2 xv  = *(const float2*)(xb  + (size_t)cc * HW + p);
                        float2 t8v = *(const float2*)(t8b + (size_t)(cc & 3) * HW + p);
                        float2 o = make_float2(
                            fmaf(acc[mi][ni][2 * h],     SC, xv.x * t8v.x),
                            fmaf(acc[mi][ni][2 * h + 1], SC, xv.y * t8v.y));
                        *(float2*)(outb + (size_t)cc * HW + p) = o;
                    }
                }
            }
        }
        __syncthreads();
    }
}

// ---------------------------------------------------------------------------
extern "C" void kernel_launch(void* const* d_in, const int* in_sizes, int n_in,
                              void* d_out, int out_size) {
    const float* x      = (const float*)d_in[0];
    const float* p2w    = (const float*)d_in[1];
    const float* p5w    = (const float*)d_in[2];
    const float* conv_w = (const float*)d_in[3];
    float* out = (float*)d_out;

    cudaFuncSetAttribute(gemm1_kernel, cudaFuncAttributeMaxDynamicSharedMemorySize, SMEM1);
    cudaFuncSetAttribute(gemm2_kernel, cudaFuncAttributeMaxDynamicSharedMemorySize, SMEM2);

    prep_kernel<<<dim3(98, NB), 256>>>(x, p5w, conv_w);
    gemm1_kernel<<<dim3(3, NB, NSPLIT), 256, SMEM1>>>(x, p2w);
    t7sum_kernel<<<1536, 256>>>();
    gemm2_kernel<<<G2_GRID, 256, SMEM2>>>(x, out);
}

// round 16
// speedup vs baseline: 2.3811x; 1.2301x over previous
#include <cuda_runtime.h>
#include <cuda_fp16.h>
#include <cstdint>

#define NB 32
#define C 128
#define HW 3136
#define K3 384
#define NSPLIT 3
#define SPL ((size_t)NB * C * K3)

// A tiles: 128 rows x 32 fp16 = 64B + 16 pad = 80B stride (single plane)
#define RSA 80
#define TILE_A (128 * RSA)                    // 10240
// gemm1 B tile: 128 rows(m) x 32 fp16 k-cols = 64B + 16 pad = 80B stride
#define RSB1 80
#define TILE_B1 (128 * RSB1)                  // 10240
// gemm2 B tile (transposed): 32 rows(m) x 128 p fp16 = 256B + 16 pad
#define RSB 272
#define TILE_B2 (32 * RSB)                    // 8704
#define STAGE1 (TILE_A + TILE_B1)             // 20480
#define STAGE2 (TILE_A + TILE_B2)             // 18944
#define SMEM1 (2 * STAGE1 + 1024)             // 41984
#define SMEM2 (2 * STAGE2 + 1024)             // 38912

#define G2_TILES 800
#define G2_GRID 592

__device__ float g_t8[NB * 4 * HW];
__device__ float g_t7p[NSPLIT * NB * C * K3];
__device__ __half g_t6h[(size_t)NB * C * HW];
__device__ __half g_t7h[(size_t)NB * C * K3];

// ---------------- helpers ----------------
__device__ __forceinline__ uint32_t smem_u32(const void* p) {
    uint32_t a;
    asm("{ .reg .u64 t; cvta.to.shared.u64 t, %1; cvt.u32.u64 %0, t; }" : "=r"(a) : "l"(p));
    return a;
}
#define CP16(dst, src) \
    asm volatile("cp.async.cg.shared.global [%0], [%1], 16;" :: "r"(dst), "l"(src))
#define CP_COMMIT() asm volatile("cp.async.commit_group;" ::: "memory")
#define CP_WAIT0()  asm volatile("cp.async.wait_group 0;" ::: "memory")

__device__ __forceinline__ void ldsm4(uint32_t addr, uint32_t* r) {
    asm volatile("ldmatrix.sync.aligned.m8n8.x4.shared.b16 {%0,%1,%2,%3}, [%4];"
                 : "=r"(r[0]), "=r"(r[1]), "=r"(r[2]), "=r"(r[3]) : "r"(addr));
}
__device__ __forceinline__ void ldsm4t(uint32_t addr, uint32_t* r) {
    asm volatile("ldmatrix.sync.aligned.m8n8.x4.trans.shared.b16 {%0,%1,%2,%3}, [%4];"
                 : "=r"(r[0]), "=r"(r[1]), "=r"(r[2]), "=r"(r[3]) : "r"(addr));
}
__device__ __forceinline__ void mma16816(float* c, const uint32_t a[4],
                                         uint32_t b0, uint32_t b1) {
    asm volatile(
        "mma.sync.aligned.m16n8k16.row.col.f32.f16.f16.f32 "
        "{%0,%1,%2,%3}, {%4,%5,%6,%7}, {%8,%9}, {%0,%1,%2,%3};"
        : "+f"(c[0]), "+f"(c[1]), "+f"(c[2]), "+f"(c[3])
        : "r"(a[0]), "r"(a[1]), "r"(a[2]), "r"(a[3]), "r"(b0), "r"(b1));
}
__device__ __forceinline__ uint2 pack4h(const float v[4]) {
    __half h0 = __float2half(v[0]), h1 = __float2half(v[1]);
    __half h2 = __float2half(v[2]), h3 = __float2half(v[3]);
    uint2 r;
    r.x = (uint32_t)__half_as_ushort(h0) | ((uint32_t)__half_as_ushort(h1) << 16);
    r.y = (uint32_t)__half_as_ushort(h2) | ((uint32_t)__half_as_ushort(h3) << 16);
    return r;
}

// cp.async one A tile: 128 rows x 64B from a packed fp16 plane
__device__ __forceinline__ void cpA(char* Asp, const __half* src, size_t rstride,
                                    int col0, int tid) {
    #pragma unroll
    for (int it = 0; it < 2; it++) {
        int idx = tid + it * 256;            // 0..511
        int r = idx >> 2, s = idx & 3;
        CP16(smem_u32(Asp + r * RSA + s * 16),
             src + (size_t)r * rstride + col0 + s * 8);
    }
}

// single product pass over preloaded fragments
#define MMA_PASS1(acc, ah, bh)                                          \
    do {                                                                \
        _Pragma("unroll")                                               \
        for (int mi = 0; mi < 2; mi++)                                  \
            _Pragma("unroll")                                           \
            for (int nq = 0; nq < 4; nq++) {                            \
                mma16816(acc[mi][nq * 2],     ah[mi], bh[nq][0], bh[nq][1]); \
                mma16816(acc[mi][nq * 2 + 1], ah[mi], bh[nq][2], bh[nq][3]); \
            }                                                           \
    } while (0)

__device__ __forceinline__ void mma_g1(uint32_t As, uint32_t Bs, int wr, int wc,
                                       int lane, float acc[2][8][4]) {
    const uint32_t a_row = (uint32_t)(wr * 32 + (lane & 15)) * RSA + ((lane >> 4) << 4);
    const int brow = (lane & 7) + ((lane & 16) >> 1);
    const uint32_t b_k = (uint32_t)((lane & 8) << 1);
    #pragma unroll
    for (int ks = 0; ks < 2; ks++) {
        uint32_t k16 = ks * 32;
        uint32_t ah[2][4], bh[4][4];
        #pragma unroll
        for (int mi = 0; mi < 2; mi++)
            ldsm4(As + a_row + (uint32_t)(mi * 16) * RSA + k16, ah[mi]);
        #pragma unroll
        for (int nq = 0; nq < 4; nq++)
            ldsm4(Bs + (uint32_t)(wc * 64 + nq * 16 + brow) * RSB1 + k16 + b_k,
                  bh[nq]);
        MMA_PASS1(acc, ah, bh);
    }
}

__device__ __forceinline__ void mma_g2(uint32_t As, uint32_t Bs, int wr, int wc,
                                       int lane, float acc[2][8][4]) {
    const uint32_t a_row = (uint32_t)(wr * 32 + (lane & 15)) * RSA + ((lane >> 4) << 4);
    const uint32_t b_row = (uint32_t)((lane & 7) + (lane & 8));
    const uint32_t b_pofs = (uint32_t)((lane & 16));
    #pragma unroll
    for (int ks = 0; ks < 2; ks++) {
        uint32_t k16 = ks * 32;
        uint32_t mb = ks * 16;
        uint32_t ah[2][4], bh[4][4];
        #pragma unroll
        for (int mi = 0; mi < 2; mi++)
            ldsm4(As + a_row + (uint32_t)(mi * 16) * RSA + k16, ah[mi]);
        #pragma unroll
        for (int nq = 0; nq < 4; nq++)
            ldsm4t(Bs + (mb + b_row) * RSB
                   + (uint32_t)(wc * 64 + nq * 16) * 2 + b_pofs, bh[nq]);
        MMA_PASS1(acc, ah, bh);
    }
}

// ---------------------------------------------------------------------------
// prep: t8 reduction + packed t6 fp16 plane. grid (98, 32) x 256
// ---------------------------------------------------------------------------
__global__ void __launch_bounds__(256) prep_kernel(const float* __restrict__ x,
                                                   const float* __restrict__ p5w,
                                                   const float* __restrict__ conv_w) {
    __shared__ float red[8][4][32];
    int n = blockIdx.y;
    int tid = threadIdx.x;
    int pl = tid & 31, q = tid >> 5;
    int p = blockIdx.x * 32 + pl;
    int rp = (p >= 56) ? (p - 56) : (p + 3080);

    const float* xb = x + (size_t)n * C * HW;
    __half* t6h = g_t6h + (size_t)n * C * HW;

    float s0 = 0.f, s1 = 0.f, s2 = 0.f, s3 = 0.f;
    int c0 = q * 16;
    #pragma unroll 4
    for (int i = 0; i < 16; i++) {
        int c = c0 + i;
        float xp = xb[(size_t)c * HW + p];
        float xr = xb[(size_t)c * HW + rp];
        t6h[(size_t)c * HW + p] = __float2half(xp + xr);
        float t = __ldg(&p5w[c]) * xr;
        s0 = fmaf(__ldg(&conv_w[c]),       t, s0);
        s1 = fmaf(__ldg(&conv_w[128 + c]), t, s1);
        s2 = fmaf(__ldg(&conv_w[256 + c]), t, s2);
        s3 = fmaf(__ldg(&conv_w[384 + c]), t, s3);
    }
    red[q][0][pl] = s0; red[q][1][pl] = s1; red[q][2][pl] = s2; red[q][3][pl] = s3;
    __syncthreads();
    if (tid < 128) {
        int j = tid >> 5, pl2 = tid & 31;
        float r = 0.f;
        #pragma unroll
        for (int qq = 0; qq < 8; qq++) r += red[qq][j][pl2];
        g_t8[((size_t)n * 4 + j) * HW + blockIdx.x * 32 + pl2] = r;
    }
}

// ---------------------------------------------------------------------------
// gemm1: D rows = c' (A = t6 plane via cp.async), cols = m. K chunks of 32.
// B = p2w*unfold_h(x) fp16. Stores UNSCALED t7 partials.
// grid (3, 32, 3) x 256, occ 2
// ---------------------------------------------------------------------------
__device__ __forceinline__ void g1_stageB(char* Bsp, const float* xb,
                                          const float* p2w, int m0, int p0, int tid) {
    int col4 = (tid & 7) * 4;
    int rbase = tid >> 3;
    #pragma unroll
    for (int pass = 0; pass < 4; pass++) {
        int mr = rbase + pass * 32;
        int m = m0 + mr, c = m / 3, k = m - 3 * c, sh = 2 * k - 2;
        float4 w4 = *reinterpret_cast<const float4*>(p2w + (size_t)m * HW + p0 + col4);
        int p = p0 + col4;
        int hh = p / 56 + sh;
        float v[4] = {0.f, 0.f, 0.f, 0.f};
        if (hh >= 0 && hh < 56) {
            float4 x4 = *reinterpret_cast<const float4*>(
                xb + (size_t)c * HW + p + sh * 56);
            v[0] = w4.x * x4.x; v[1] = w4.y * x4.y;
            v[2] = w4.z * x4.z; v[3] = w4.w * x4.w;
        }
        *(uint2*)(Bsp + mr * RSB1 + col4 * 2) = pack4h(v);
    }
}

__global__ void __launch_bounds__(256, 2) gemm1_kernel(const float* __restrict__ x,
                                                       const float* __restrict__ p2w) {
    extern __shared__ char smem_raw[];
    char* smp = (char*)(((uintptr_t)smem_raw + 1023) & ~(uintptr_t)1023);

    const int tid = threadIdx.x, lane = tid & 31, wid = tid >> 5;
    const int wr = wid >> 1, wc = wid & 1;
    const int n = blockIdx.y, m0 = blockIdx.x * 128, s = blockIdx.z;

    const float* xb = x + (size_t)n * C * HW;
    const __half* t6h = g_t6h + (size_t)n * C * HW;

    float acc[2][8][4] = {};
    const int beg[4] = {0, 33, 66, 98};
    const int nch = beg[s + 1] - beg[s];
    const int pbase = beg[s] * 32;

    cpA(smp, t6h, HW, pbase, tid);
    CP_COMMIT();
    g1_stageB(smp + TILE_A, xb, p2w, m0, pbase, tid);
    CP_WAIT0();
    __syncthreads();

    for (int ch = 0; ch < nch; ch++) {
        char* cur = smp + (ch & 1) * STAGE1;
        bool more = ch + 1 < nch;
        char* nxt = smp + ((ch + 1) & 1) * STAGE1;
        int pn = pbase + (ch + 1) * 32;
        if (more) { cpA(nxt, t6h, HW, pn, tid); CP_COMMIT(); }
        mma_g1(smem_u32(cur), smem_u32(cur + TILE_A), wr, wc, lane, acc);
        if (more) g1_stageB(nxt + TILE_A, xb, p2w, m0, pn, tid);
        CP_WAIT0();
        __syncthreads();
    }

    // store UNSCALED partials (scale applied in gemm2 epilogue)
    float* ob = g_t7p + ((size_t)(s * NB + n)) * C * K3;
    #pragma unroll
    for (int mi = 0; mi < 2; mi++) {
        #pragma unroll
        for (int ni = 0; ni < 8; ni++) {
            int row = wr * 32 + mi * 16 + (lane >> 2);
            int col = m0 + wc * 64 + ni * 8 + (lane & 3) * 2;
            *(float2*)(ob + (size_t)row * K3 + col) =
                make_float2(acc[mi][ni][0], acc[mi][ni][1]);
            *(float2*)(ob + (size_t)(row + 8) * K3 + col) =
                make_float2(acc[mi][ni][2], acc[mi][ni][3]);
        }
    }
}

// ---------------------------------------------------------------------------
// t7sum: sum 3 partials, pack to fp16 plane (unscaled). grid 1536
// ---------------------------------------------------------------------------
__global__ void __launch_bounds__(256) t7sum_kernel() {
    size_t i = ((size_t)blockIdx.x * 256 + threadIdx.x) * 4;
    float4 v0 = *(const float4*)(g_t7p + i);
    float4 v1 = *(const float4*)(g_t7p + SPL + i);
    float4 v2 = *(const float4*)(g_t7p + 2 * SPL + i);
    float v[4] = {v0.x + v1.x + v2.x, v0.y + v1.y + v2.y,
                  v0.z + v1.z + v2.z, v0.w + v1.w + v2.w};
    *(uint2*)(g_t7h + i) = pack4h(v);
}

// ---------------------------------------------------------------------------
// gemm2: persistent grid 592, static stride.
// D rows = c (A = t7 plane via cp.async), cols = p. B = unfold_w(x) fp16.
// Epilogue applies SC and fuses t9.
// ---------------------------------------------------------------------------
__device__ __forceinline__ void g2_stageB(char* Bsp, const float* xb,
                                          int p0, int m0c, int tid) {
    int mrow = tid & 31;
    int pq = tid >> 5;
    int m = m0c + mrow, cp = m / 3, k = m - 3 * cp, sh = 2 * k - 2;
    int pbase = p0 + pq * 16;
    const float* src = xb + (size_t)cp * HW + pbase + sh;

    float v[16];
    #pragma unroll
    for (int j = 0; j < 8; j++) {
        int p = pbase + 2 * j;
        int wcol = p % 56;
        int ww = wcol + sh;
        bool ok = (p < HW) && (ww >= 0) && (ww < 56);
        float2 f = ok ? *(const float2*)(src + 2 * j) : make_float2(0.f, 0.f);
        v[2 * j] = f.x; v[2 * j + 1] = f.y;
    }
    uint2 h0 = pack4h(v), h1 = pack4h(v + 4), h2 = pack4h(v + 8), h3 = pack4h(v + 12);
    char* bh = Bsp + mrow * RSB + pq * 32;
    *(uint4*)(bh)      = make_uint4(h0.x, h0.y, h1.x, h1.y);
    *(uint4*)(bh + 16) = make_uint4(h2.x, h2.y, h3.x, h3.y);
}

__global__ void __launch_bounds__(256, 2) gemm2_kernel(const float* __restrict__ x,
                                                       float* __restrict__ out) {
    extern __shared__ char smem_raw[];
    char* smp = (char*)(((uintptr_t)smem_raw + 1023) & ~(uintptr_t)1023);

    const int tid = threadIdx.x, lane = tid & 31, wid = tid >> 5;
    const int wr = wid >> 1, wc = wid & 1;
    const int NCH = 12;
    const float SC = 9.1126371e-4f;   // 1/(sqrt(3136)*sqrt(384))

    for (int tile = blockIdx.x; tile < G2_TILES; tile += G2_GRID) {
        const int n = tile / 25;
        const int p0 = (tile - n * 25) * 128;

        const float* xb = x + (size_t)n * C * HW;
        const __half* t7h = g_t7h + (size_t)n * C * K3;

        float acc[2][8][4] = {};

        cpA(smp, t7h, K3, 0, tid);
        CP_COMMIT();
        g2_stageB(smp + TILE_A, xb, p0, 0, tid);
        CP_WAIT0();
        __syncthreads();

        for (int ch = 0; ch < NCH; ch++) {
            char* cur = smp + (ch & 1) * STAGE2;
            bool more = ch + 1 < NCH;
            char* nxt = smp + ((ch + 1) & 1) * STAGE2;
            int mn = (ch + 1) * 32;
            if (more) { cpA(nxt, t7h, K3, mn, tid); CP_COMMIT(); }
            mma_g2(smem_u32(cur), smem_u32(cur + TILE_A), wr, wc, lane, acc);
            if (more) g2_stageB(nxt + TILE_A, xb, p0, mn, tid);
            CP_WAIT0();
            __syncthreads();
        }

        // epilogue: out = SC*acc + x * t8[c%4]
        const float* t8b = g_t8 + (size_t)n * 4 * HW;
        float* outb = out + (size_t)n * C * HW;
        #pragma unroll
        for (int mi = 0; mi < 2; mi++) {
            #pragma unroll
            for (int ni = 0; ni < 8; ni++) {
                int c = wr * 32 + mi * 16 + (lane >> 2);
                int p = p0 + wc * 64 + ni * 8 + (lane & 3) * 2;
                if (p < HW) {
                    #pragma unroll
                    for (int h = 0; h < 2; h++) {
                        int cc = c + h * 8;
                        float2 xv  = *(const float2*)(xb  + (size_t)cc * HW + p);
                        float2 t8v = *(const float2*)(t8b + (size_t)(cc & 3) * HW + p);
                        float2 o = make_float2(
                            fmaf(acc[mi][ni][2 * h],     SC, xv.x * t8v.x),
                            fmaf(acc[mi][ni][2 * h + 1], SC, xv.y * t8v.y));
                        *(float2*)(outb + (size_t)cc * HW + p) = o;
                    }
                }
            }
        }
        __syncthreads();
    }
}

// ---------------------------------------------------------------------------
extern "C" void kernel_launch(void* const* d_in, const int* in_sizes, int n_in,
                              void* d_out, int out_size) {
    const float* x      = (const float*)d_in[0];
    const float* p2w    = (const float*)d_in[1];
    const float* p5w    = (const float*)d_in[2];
    const float* conv_w = (const float*)d_in[3];
    float* out = (float*)d_out;

    cudaFuncSetAttribute(gemm1_kernel, cudaFuncAttributeMaxDynamicSharedMemorySize, SMEM1);
    cudaFuncSetAttribute(gemm2_kernel, cudaFuncAttributeMaxDynamicSharedMemorySize, SMEM2);

    prep_kernel<<<dim3(98, NB), 256>>>(x, p5w, conv_w);
    gemm1_kernel<<<dim3(3, NB, NSPLIT), 256, SMEM1>>>(x, p2w);
    t7sum_kernel<<<1536, 256>>>();
    gemm2_kernel<<<G2_GRID, 256, SMEM2>>>(x, out);
}

// round 17
// speedup vs baseline: 2.5974x; 1.0909x over previous
#include <cuda_runtime.h>
#include <cuda_fp16.h>
#include <cstdint>

#define NB 32
#define C 128
#define HW 3136
#define K3 384
#define NSPLIT 3
#define SPL ((size_t)NB * C * K3)

// A tiles: 128 rows x 32 fp16 = 64B + 16 pad = 80B stride (single plane)
#define RSA 80
#define TILE_A (128 * RSA)                    // 10240
// gemm1 B tile: 128 rows(m) x 32 fp16 k-cols = 64B + 16 pad = 80B stride
#define RSB1 80
#define TILE_B1 (128 * RSB1)                  // 10240
// gemm2 B tile (transposed): 32 rows(m) x 128 p fp16 = 256B + 16 pad
#define RSB 272
#define TILE_B2 (32 * RSB)                    // 8704
#define STAGE1 (TILE_A + TILE_B1)             // 20480
#define STAGE2 (TILE_A + TILE_B2)             // 18944
#define SMEM1 (2 * STAGE1 + 1024)             // 41984
#define SMEM2 (2 * STAGE2 + 1024)             // 38912

#define G2_TILES 800
#define G2_GRID 592

__device__ float g_t8[NB * 4 * HW];
__device__ float g_t7p[NSPLIT * NB * C * K3];
__device__ __half g_t6h[(size_t)NB * C * HW];
__device__ __half g_t7h[(size_t)NB * C * K3];

// ---------------- helpers ----------------
__device__ __forceinline__ uint32_t smem_u32(const void* p) {
    uint32_t a;
    asm("{ .reg .u64 t; cvta.to.shared.u64 t, %1; cvt.u32.u64 %0, t; }" : "=r"(a) : "l"(p));
    return a;
}
#define CP16(dst, src) \
    asm volatile("cp.async.cg.shared.global [%0], [%1], 16;" :: "r"(dst), "l"(src))
#define CP_COMMIT() asm volatile("cp.async.commit_group;" ::: "memory")
#define CP_WAIT0()  asm volatile("cp.async.wait_group 0;" ::: "memory")

__device__ __forceinline__ void ldsm4(uint32_t addr, uint32_t* r) {
    asm volatile("ldmatrix.sync.aligned.m8n8.x4.shared.b16 {%0,%1,%2,%3}, [%4];"
                 : "=r"(r[0]), "=r"(r[1]), "=r"(r[2]), "=r"(r[3]) : "r"(addr));
}
__device__ __forceinline__ void ldsm4t(uint32_t addr, uint32_t* r) {
    asm volatile("ldmatrix.sync.aligned.m8n8.x4.trans.shared.b16 {%0,%1,%2,%3}, [%4];"
                 : "=r"(r[0]), "=r"(r[1]), "=r"(r[2]), "=r"(r[3]) : "r"(addr));
}
__device__ __forceinline__ void mma16816(float* c, const uint32_t a[4],
                                         uint32_t b0, uint32_t b1) {
    asm volatile(
        "mma.sync.aligned.m16n8k16.row.col.f32.f16.f16.f32 "
        "{%0,%1,%2,%3}, {%4,%5,%6,%7}, {%8,%9}, {%0,%1,%2,%3};"
        : "+f"(c[0]), "+f"(c[1]), "+f"(c[2]), "+f"(c[3])
        : "r"(a[0]), "r"(a[1]), "r"(a[2]), "r"(a[3]), "r"(b0), "r"(b1));
}
__device__ __forceinline__ uint2 pack4h(const float v[4]) {
    __half h0 = __float2half(v[0]), h1 = __float2half(v[1]);
    __half h2 = __float2half(v[2]), h3 = __float2half(v[3]);
    uint2 r;
    r.x = (uint32_t)__half_as_ushort(h0) | ((uint32_t)__half_as_ushort(h1) << 16);
    r.y = (uint32_t)__half_as_ushort(h2) | ((uint32_t)__half_as_ushort(h3) << 16);
    return r;
}

// cp.async one A tile: 128 rows x 64B from a packed fp16 plane
__device__ __forceinline__ void cpA(char* Asp, const __half* src, size_t rstride,
                                    int col0, int tid) {
    #pragma unroll
    for (int it = 0; it < 2; it++) {
        int idx = tid + it * 256;            // 0..511
        int r = idx >> 2, s = idx & 3;
        CP16(smem_u32(Asp + r * RSA + s * 16),
             src + (size_t)r * rstride + col0 + s * 8);
    }
}

// single product pass over preloaded fragments
#define MMA_PASS1(acc, ah, bh)                                          \
    do {                                                                \
        _Pragma("unroll")                                               \
        for (int mi = 0; mi < 2; mi++)                                  \
            _Pragma("unroll")                                           \
            for (int nq = 0; nq < 4; nq++) {                            \
                mma16816(acc[mi][nq * 2],     ah[mi], bh[nq][0], bh[nq][1]); \
                mma16816(acc[mi][nq * 2 + 1], ah[mi], bh[nq][2], bh[nq][3]); \
            }                                                           \
    } while (0)

__device__ __forceinline__ void mma_g1(uint32_t As, uint32_t Bs, int wr, int wc,
                                       int lane, float acc[2][8][4]) {
    const uint32_t a_row = (uint32_t)(wr * 32 + (lane & 15)) * RSA + ((lane >> 4) << 4);
    const int brow = (lane & 7) + ((lane & 16) >> 1);
    const uint32_t b_k = (uint32_t)((lane & 8) << 1);
    #pragma unroll
    for (int ks = 0; ks < 2; ks++) {
        uint32_t k16 = ks * 32;
        uint32_t ah[2][4], bh[4][4];
        #pragma unroll
        for (int mi = 0; mi < 2; mi++)
            ldsm4(As + a_row + (uint32_t)(mi * 16) * RSA + k16, ah[mi]);
        #pragma unroll
        for (int nq = 0; nq < 4; nq++)
            ldsm4(Bs + (uint32_t)(wc * 64 + nq * 16 + brow) * RSB1 + k16 + b_k,
                  bh[nq]);
        MMA_PASS1(acc, ah, bh);
    }
}

__device__ __forceinline__ void mma_g2(uint32_t As, uint32_t Bs, int wr, int wc,
                                       int lane, float acc[2][8][4]) {
    const uint32_t a_row = (uint32_t)(wr * 32 + (lane & 15)) * RSA + ((lane >> 4) << 4);
    const uint32_t b_row = (uint32_t)((lane & 7) + (lane & 8));
    const uint32_t b_pofs = (uint32_t)((lane & 16));
    #pragma unroll
    for (int ks = 0; ks < 2; ks++) {
        uint32_t k16 = ks * 32;
        uint32_t mb = ks * 16;
        uint32_t ah[2][4], bh[4][4];
        #pragma unroll
        for (int mi = 0; mi < 2; mi++)
            ldsm4(As + a_row + (uint32_t)(mi * 16) * RSA + k16, ah[mi]);
        #pragma unroll
        for (int nq = 0; nq < 4; nq++)
            ldsm4t(Bs + (mb + b_row) * RSB
                   + (uint32_t)(wc * 64 + nq * 16) * 2 + b_pofs, bh[nq]);
        MMA_PASS1(acc, ah, bh);
    }
}

// ---------------------------------------------------------------------------
// prep: t8 reduction + packed t6 fp16 plane. grid (98, 32) x 256
// ---------------------------------------------------------------------------
__global__ void __launch_bounds__(256) prep_kernel(const float* __restrict__ x,
                                                   const float* __restrict__ p5w,
                                                   const float* __restrict__ conv_w) {
    __shared__ float red[8][4][32];
    int n = blockIdx.y;
    int tid = threadIdx.x;
    int pl = tid & 31, q = tid >> 5;
    int p = blockIdx.x * 32 + pl;
    int rp = (p >= 56) ? (p - 56) : (p + 3080);

    const float* xb = x + (size_t)n * C * HW;
    __half* t6h = g_t6h + (size_t)n * C * HW;

    float s0 = 0.f, s1 = 0.f, s2 = 0.f, s3 = 0.f;
    int c0 = q * 16;
    #pragma unroll 4
    for (int i = 0; i < 16; i++) {
        int c = c0 + i;
        float xp = xb[(size_t)c * HW + p];
        float xr = xb[(size_t)c * HW + rp];
        t6h[(size_t)c * HW + p] = __float2half(xp + xr);
        float t = __ldg(&p5w[c]) * xr;
        s0 = fmaf(__ldg(&conv_w[c]),       t, s0);
        s1 = fmaf(__ldg(&conv_w[128 + c]), t, s1);
        s2 = fmaf(__ldg(&conv_w[256 + c]), t, s2);
        s3 = fmaf(__ldg(&conv_w[384 + c]), t, s3);
    }
    red[q][0][pl] = s0; red[q][1][pl] = s1; red[q][2][pl] = s2; red[q][3][pl] = s3;
    __syncthreads();
    if (tid < 128) {
        int j = tid >> 5, pl2 = tid & 31;
        float r = 0.f;
        #pragma unroll
        for (int qq = 0; qq < 8; qq++) r += red[qq][j][pl2];
        g_t8[((size_t)n * 4 + j) * HW + blockIdx.x * 32 + pl2] = r;
    }
}

// ---------------------------------------------------------------------------
// gemm1: D rows = c' (A = t6 plane via cp.async), cols = m. K chunks of 32.
// B = p2w*unfold_h(x) fp16. Stores UNSCALED t7 partials.
// grid (3, 32, 3) x 256, occ 2
// ---------------------------------------------------------------------------
__device__ __forceinline__ void g1_stageB(char* Bsp, const float* xb,
                                          const float* p2w, int m0, int p0, int tid) {
    int col4 = (tid & 7) * 4;
    int rbase = tid >> 3;
    #pragma unroll
    for (int pass = 0; pass < 4; pass++) {
        int mr = rbase + pass * 32;
        int m = m0 + mr, c = m / 3, k = m - 3 * c, sh = 2 * k - 2;
        float4 w4 = *reinterpret_cast<const float4*>(p2w + (size_t)m * HW + p0 + col4);
        int p = p0 + col4;
        int hh = p / 56 + sh;
        float v[4] = {0.f, 0.f, 0.f, 0.f};
        if (hh >= 0 && hh < 56) {
            float4 x4 = *reinterpret_cast<const float4*>(
                xb + (size_t)c * HW + p + sh * 56);
            v[0] = w4.x * x4.x; v[1] = w4.y * x4.y;
            v[2] = w4.z * x4.z; v[3] = w4.w * x4.w;
        }
        *(uint2*)(Bsp + mr * RSB1 + col4 * 2) = pack4h(v);
    }
}

__global__ void __launch_bounds__(256, 2) gemm1_kernel(const float* __restrict__ x,
                                                       const float* __restrict__ p2w) {
    extern __shared__ char smem_raw[];
    char* smp = (char*)(((uintptr_t)smem_raw + 1023) & ~(uintptr_t)1023);

    const int tid = threadIdx.x, lane = tid & 31, wid = tid >> 5;
    const int wr = wid >> 1, wc = wid & 1;
    const int n = blockIdx.y, m0 = blockIdx.x * 128, s = blockIdx.z;

    const float* xb = x + (size_t)n * C * HW;
    const __half* t6h = g_t6h + (size_t)n * C * HW;

    float acc[2][8][4] = {};
    const int beg[4] = {0, 33, 66, 98};
    const int nch = beg[s + 1] - beg[s];
    const int pbase = beg[s] * 32;

    cpA(smp, t6h, HW, pbase, tid);
    CP_COMMIT();
    g1_stageB(smp + TILE_A, xb, p2w, m0, pbase, tid);
    CP_WAIT0();
    __syncthreads();

    for (int ch = 0; ch < nch; ch++) {
        char* cur = smp + (ch & 1) * STAGE1;
        bool more = ch + 1 < nch;
        char* nxt = smp + ((ch + 1) & 1) * STAGE1;
        int pn = pbase + (ch + 1) * 32;
        if (more) { cpA(nxt, t6h, HW, pn, tid); CP_COMMIT(); }
        mma_g1(smem_u32(cur), smem_u32(cur + TILE_A), wr, wc, lane, acc);
        if (more) g1_stageB(nxt + TILE_A, xb, p2w, m0, pn, tid);
        CP_WAIT0();
        __syncthreads();
    }

    // store UNSCALED partials (scale applied in gemm2 epilogue)
    float* ob = g_t7p + ((size_t)(s * NB + n)) * C * K3;
    #pragma unroll
    for (int mi = 0; mi < 2; mi++) {
        #pragma unroll
        for (int ni = 0; ni < 8; ni++) {
            int row = wr * 32 + mi * 16 + (lane >> 2);
            int col = m0 + wc * 64 + ni * 8 + (lane & 3) * 2;
            *(float2*)(ob + (size_t)row * K3 + col) =
                make_float2(acc[mi][ni][0], acc[mi][ni][1]);
            *(float2*)(ob + (size_t)(row + 8) * K3 + col) =
                make_float2(acc[mi][ni][2], acc[mi][ni][3]);
        }
    }
}

// ---------------------------------------------------------------------------
// t7sum: sum 3 partials, pack to fp16 plane (unscaled). grid 1536
// ---------------------------------------------------------------------------
__global__ void __launch_bounds__(256) t7sum_kernel() {
    size_t i = ((size_t)blockIdx.x * 256 + threadIdx.x) * 4;
    float4 v0 = *(const float4*)(g_t7p + i);
    float4 v1 = *(const float4*)(g_t7p + SPL + i);
    float4 v2 = *(const float4*)(g_t7p + 2 * SPL + i);
    float v[4] = {v0.x + v1.x + v2.x, v0.y + v1.y + v2.y,
                  v0.z + v1.z + v2.z, v0.w + v1.w + v2.w};
    *(uint2*)(g_t7h + i) = pack4h(v);
}

// ---------------------------------------------------------------------------
// gemm2: persistent grid 592, static stride.
// D rows = c (A = t7 plane via cp.async), cols = p. B = unfold_w(x) fp16.
// B staging: warp-per-row coalesced (32 lanes read 256B contiguous).
// ---------------------------------------------------------------------------
__device__ __forceinline__ void g2_stageB(char* Bsp, const float* xb,
                                          int p0, int m0c, int tid) {
    int w = tid >> 5, lane = tid & 31;
    #pragma unroll
    for (int rr = 0; rr < 4; rr++) {
        int mrow = w * 4 + rr;
        int m = m0c + mrow, cp = m / 3, k = m - 3 * cp, sh = 2 * k - 2;
        const float* src = xb + (size_t)cp * HW + p0 + sh;
        #pragma unroll
        for (int half = 0; half < 2; half++) {
            int pl = half * 64 + lane * 2;
            int p = p0 + pl;
            int wcol = p % 56;
            int ww = wcol + sh;
            bool ok = (p < HW) && (ww >= 0) && (ww < 56);
            float2 f = ok ? *(const float2*)(src + pl) : make_float2(0.f, 0.f);
            __half2 h2v = __floats2half2_rn(f.x, f.y);
            *(uint32_t*)(Bsp + mrow * RSB + pl * 2) =
                *reinterpret_cast<uint32_t*>(&h2v);
        }
    }
}

__global__ void __launch_bounds__(256, 2) gemm2_kernel(const float* __restrict__ x,
                                                       float* __restrict__ out) {
    extern __shared__ char smem_raw[];
    char* smp = (char*)(((uintptr_t)smem_raw + 1023) & ~(uintptr_t)1023);

    const int tid = threadIdx.x, lane = tid & 31, wid = tid >> 5;
    const int wr = wid >> 1, wc = wid & 1;
    const int NCH = 12;
    const float SC = 9.1126371e-4f;   // 1/(sqrt(3136)*sqrt(384))

    for (int tile = blockIdx.x; tile < G2_TILES; tile += G2_GRID) {
        const int n = tile / 25;
        const int p0 = (tile - n * 25) * 128;

        const float* xb = x + (size_t)n * C * HW;
        const __half* t7h = g_t7h + (size_t)n * C * K3;

        float acc[2][8][4] = {};

        cpA(smp, t7h, K3, 0, tid);
        CP_COMMIT();
        g2_stageB(smp + TILE_A, xb, p0, 0, tid);
        CP_WAIT0();
        __syncthreads();

        for (int ch = 0; ch < NCH; ch++) {
            char* cur = smp + (ch & 1) * STAGE2;
            bool more = ch + 1 < NCH;
            char* nxt = smp + ((ch + 1) & 1) * STAGE2;
            int mn = (ch + 1) * 32;
            if (more) { cpA(nxt, t7h, K3, mn, tid); CP_COMMIT(); }
            mma_g2(smem_u32(cur), smem_u32(cur + TILE_A), wr, wc, lane, acc);
            if (more) g2_stageB(nxt + TILE_A, xb, p0, mn, tid);
            CP_WAIT0();
            __syncthreads();
        }

        // epilogue: out = SC*acc + x * t8[c%4]
        const float* t8b = g_t8 + (size_t)n * 4 * HW;
        float* outb = out + (size_t)n * C * HW;
        #pragma unroll
        for (int mi = 0; mi < 2; mi++) {
            #pragma unroll
            for (int ni = 0; ni < 8; ni++) {
                int c = wr * 32 + mi * 16 + (lane >> 2);
                int p = p0 + wc * 64 + ni * 8 + (lane & 3) * 2;
                if (p < HW) {
                    #pragma unroll
                    for (int h = 0; h < 2; h++) {
                        int cc = c + h * 8;
                        float2 xv  = *(const float2*)(xb  + (size_t)cc * HW + p);
                        float2 t8v = *(const float2*)(t8b + (size_t)(cc & 3) * HW + p);
                        float2 o = make_float2(
                            fmaf(acc[mi][ni][2 * h],     SC, xv.x * t8v.x),
                            fmaf(acc[mi][ni][2 * h + 1], SC, xv.y * t8v.y));
                        *(float2*)(outb + (size_t)cc * HW + p) = o;
                    }
                }
            }
        }
        __syncthreads();
    }
}

// ---------------------------------------------------------------------------
extern "C" void kernel_launch(void* const* d_in, const int* in_sizes, int n_in,
                              void* d_out, int out_size) {
    const float* x      = (const float*)d_in[0];
    const float* p2w    = (const float*)d_in[1];
    const float* p5w    = (const float*)d_in[2];
    const float* conv_w = (const float*)d_in[3];
    float* out = (float*)d_out;

    cudaFuncSetAttribute(gemm1_kernel, cudaFuncAttributeMaxDynamicSharedMemorySize, SMEM1);
    cudaFuncSetAttribute(gemm2_kernel, cudaFuncAttributeMaxDynamicSharedMemorySize, SMEM2);

    prep_kernel<<<dim3(98, NB), 256>>>(x, p5w, conv_w);
    gemm1_kernel<<<dim3(3, NB, NSPLIT), 256, SMEM1>>>(x, p2w);
    t7sum_kernel<<<1536, 256>>>();
    gemm2_kernel<<<G2_GRID, 256, SMEM2>>>(x, out);
}